// round 12
// baseline (speedup 1.0000x reference)
#include <cuda_runtime.h>
#include <cstdint>

// Problem constants
#define BB    16
#define CC    8
#define DD    511
#define DIMN  2048
#define SEQ   512
#define NH    16
#define HD    128
#define HWSZ  256
#define XB    (CC*DD*HWSZ)   // 1046528  (x batch stride)
#define XC    (DD*HWSZ)      // 130816   (x channel stride)
#define QLD   6144           // qkv_w leading dim (row length)
#define SCALE 0.08838834764831845f  // 128^-0.5

// Scratch (static device globals; no allocation anywhere)
__device__ float g_qp[32*DIMN];        // split-K partials for q
__device__ float g_q[DIMN];            // q for cls token (batch-independent)
__device__ float g_qhat[NH*DIMN];      // scale * Wk_h^T q_h
__device__ float g_sc[BB*NH*SEQ];      // scores -> probs (in place)
__device__ float g_tp[4][BB*NH*DIMN];  // s-split partials of t = P @ tok
__device__ float g_t[BB*NH*DIMN];      // t = P @ tok
__device__ float g_aop[16][BB*DIMN];   // d-chunk partials of attn out @ Wv
__device__ float g_ao[BB*DIMN];        // attention output (pre-proj)
__device__ float g_outp[16][BB*DIMN];  // d-chunk partials of final proj

// cp.async helpers (16B, bypass-L1 .cg path)
__device__ __forceinline__ void cpa16(void* smem_dst, const void* gsrc) {
    uint32_t sa = (uint32_t)__cvta_generic_to_shared(smem_dst);
    asm volatile("cp.async.cg.shared.global [%0], [%1], 16;" :: "r"(sa), "l"(gsrc));
}
__device__ __forceinline__ void cpa_commit() {
    asm volatile("cp.async.commit_group;");
}
__device__ __forceinline__ void cpa_wait1() {
    asm volatile("cp.async.wait_group 1;");
}
__device__ __forceinline__ void cpa_wait0() {
    asm volatile("cp.async.wait_group 0;");
}

// ---------------------------------------------------------------------------
// Kernel 1a: split-K partial of q = tok0 @ Wq.
// grid (16 colblocks, 32 dchunks of 64 rows), block 128.
__global__ void k_q_part(const float* __restrict__ pos, const float* __restrict__ cls,
                         const float* __restrict__ qkvw) {
    __shared__ float t0[64];
    int dc = blockIdx.y;
    int tid = threadIdx.x;
    if (tid < 64) t0[tid] = cls[dc*64 + tid] + pos[dc*64 + tid];
    __syncthreads();
    int col = blockIdx.x * 128 + tid;
    const float* wp = qkvw + (dc*64)*QLD + col;
    float a0 = 0.f, a1 = 0.f, a2 = 0.f, a3 = 0.f;
    #pragma unroll 2
    for (int d = 0; d < 64; d += 8) {
        a0 += t0[d+0] * wp[(d+0)*QLD];
        a1 += t0[d+1] * wp[(d+1)*QLD];
        a2 += t0[d+2] * wp[(d+2)*QLD];
        a3 += t0[d+3] * wp[(d+3)*QLD];
        a0 += t0[d+4] * wp[(d+4)*QLD];
        a1 += t0[d+5] * wp[(d+5)*QLD];
        a2 += t0[d+6] * wp[(d+6)*QLD];
        a3 += t0[d+7] * wp[(d+7)*QLD];
    }
    g_qp[dc*DIMN + col] = (a0 + a1) + (a2 + a3);
}

// Kernel 1b: reduce the 32 partials (deterministic order) + bias. grid 16, block 128
__global__ void k_q_sum(const float* __restrict__ qkvb) {
    int col = blockIdx.x * 128 + threadIdx.x;
    float a = qkvb[col];
    #pragma unroll
    for (int dc = 0; dc < 32; dc++) a += g_qp[dc*DIMN + col];
    g_q[col] = a;
}

// ---------------------------------------------------------------------------
// Kernel 2: qhat[h, dim] = SCALE * sum_j qkv_w[dim, 2048 + h*128 + j] * q[h*128+j]
// grid (256, 16): 8 dims per CTA (one per warp), block 256, float4 loads.
__global__ void k_qhat(const float* __restrict__ qkvw) {
    int h = blockIdx.y;
    __shared__ float4 qv4[32];
    int tid = threadIdx.x;
    if (tid < 32) qv4[tid] = *reinterpret_cast<const float4*>(&g_q[h*HD + tid*4]);
    __syncthreads();
    int w = tid >> 5, lane = tid & 31;
    int dim = blockIdx.x * 8 + w;
    const float4* wr4 = reinterpret_cast<const float4*>(qkvw + dim*QLD + DIMN + h*HD);
    float4 wv = wr4[lane];
    float4 qv = qv4[lane];
    float p = wv.x*qv.x + wv.y*qv.y + wv.z*qv.z + wv.w*qv.w;
    #pragma unroll
    for (int o = 16; o; o >>= 1) p += __shfl_xor_sync(0xffffffffu, p, o);
    if (lane == 0) g_qhat[h*DIMN + dim] = p * SCALE;
}

// ---------------------------------------------------------------------------
// Kernel 3: scores[b,h,s] = qhat[h,:] . tok[b,s,:]  (tok built on the fly)
// grid (32 stiles, 16 b), block 256 (8 warps). Warp = 4 tokens x 8 heads.
// x staged via cp.async double-buffered smem tiles; pos direct LDG (L2-hot).
__global__ void __launch_bounds__(256, 3)
k_scores(const float* __restrict__ x, const float* __restrict__ pos,
         const float* __restrict__ cls) {
    int b = blockIdx.y;
    int tid = threadIdx.x, w = tid >> 5, lane = tid & 31;
    int tg = w >> 1;            // token group 0..3
    int hh = (w & 1) * 8;       // head base: 0 or 8
    int s0c = blockIdx.x * 16;  // CTA token base
    int s0 = s0c + tg * 4;      // warp token base
    __shared__ float qh[NH * 512];     // 32 KB: current 512-dim chunk, all heads
    __shared__ float xs[2][16][128];   // 16 KB: x tiles (16 tokens x 128 dims)

    // Issue cp.async for slice ci into buffer buf. 512 16B-chunks; 2 per thread.
    auto issue = [&](int ci, int buf) {
        int dn = ci * 128;
        int cn = dn >> 8, rn = dn & 255;
        #pragma unroll
        for (int u = 0; u < 2; u++) {
            int k = tid + u * 256;
            int tt = k >> 5;           // token 0..15
            int c16 = k & 31;          // 16B chunk within 512B row
            int s = s0c + tt;
            const float* src = (s == 0)
                ? (cls + dn + c16*4)
                : (x + (size_t)b*XB + cn*XC + (s-1)*HWSZ + rn + c16*4);
            cpa16(&xs[buf][tt][c16*4], src);
        }
        cpa_commit();
    };

    float acc[8][4];
    #pragma unroll
    for (int h = 0; h < 8; h++)
        #pragma unroll
        for (int j = 0; j < 4; j++) acc[h][j] = 0.f;

    issue(0, 0);

    for (int ci = 0; ci < 16; ci++) {
        int buf = ci & 1;
        if (ci < 15) issue(ci + 1, buf ^ 1);
        if (ci < 15) cpa_wait1(); else cpa_wait0();
        if ((ci & 3) == 0) {
            __syncthreads();   // prior chunk's qh readers done
            int ch = ci >> 2;
            for (int t4 = tid; t4 < NH*128; t4 += 256) {
                int h = t4 >> 7, dd4 = t4 & 127;
                *reinterpret_cast<float4*>(&qh[h*512 + dd4*4]) =
                    *reinterpret_cast<const float4*>(&g_qhat[h*DIMN + ch*512 + dd4*4]);
            }
        }
        __syncthreads();       // x tile + qh visible to all
        // compute slice ci
        int ddc = (ci & 3)*128 + lane*4;   // dim within current 512-chunk
        int d   = ci*128 + lane*4;         // absolute dim
        float4 tv[4];
        #pragma unroll
        for (int j = 0; j < 4; j++) {
            float4 xv = *reinterpret_cast<const float4*>(&xs[buf][tg*4 + j][lane*4]);
            float4 pv = *reinterpret_cast<const float4*>(&pos[(s0 + j)*DIMN + d]);
            tv[j].x = xv.x + pv.x; tv[j].y = xv.y + pv.y;
            tv[j].z = xv.z + pv.z; tv[j].w = xv.w + pv.w;
        }
        #pragma unroll
        for (int h = 0; h < 8; h++) {
            float4 qv = *reinterpret_cast<const float4*>(&qh[(hh + h)*512 + ddc]);
            #pragma unroll
            for (int j = 0; j < 4; j++) {
                acc[h][j] += qv.x*tv[j].x + qv.y*tv[j].y
                           + qv.z*tv[j].z + qv.w*tv[j].w;
            }
        }
        __syncthreads();       // all reads of this buffer done before re-issue
    }
    // butterfly reduce (32 outputs per warp)
    #pragma unroll
    for (int o = 16; o; o >>= 1)
        #pragma unroll
        for (int h = 0; h < 8; h++)
            #pragma unroll
            for (int j = 0; j < 4; j++)
                acc[h][j] += __shfl_xor_sync(0xffffffffu, acc[h][j], o);
    float outv = 0.f;
    #pragma unroll
    for (int h = 0; h < 8; h++)
        #pragma unroll
        for (int j = 0; j < 4; j++)
            if (lane == h*4 + j) outv = acc[h][j];
    int h8 = lane >> 2, j = lane & 3;
    g_sc[(b*NH + hh + h8)*SEQ + s0c + tg*4 + j] = outv;
}

// ---------------------------------------------------------------------------
// Kernel 4: softmax over s (512) per (b,h) row; adds the q.bk bias term.
// grid 256, block 128
__global__ void k_softmax(const float* __restrict__ qkvb) {
    int bh = blockIdx.x;
    int h = bh & 15;
    int tid = threadIdx.x;
    __shared__ float red[128];

    red[tid] = g_q[h*HD + tid] * qkvb[DIMN + h*HD + tid];
    __syncthreads();
    for (int o = 64; o; o >>= 1) { if (tid < o) red[tid] += red[tid + o]; __syncthreads(); }
    float sbias = red[0] * SCALE;
    __syncthreads();

    float* row = g_sc + bh*SEQ;
    float v[4];
    float m = -1e30f;
    #pragma unroll
    for (int j = 0; j < 4; j++) { v[j] = row[tid + j*128] + sbias; m = fmaxf(m, v[j]); }
    red[tid] = m; __syncthreads();
    for (int o = 64; o; o >>= 1) { if (tid < o) red[tid] = fmaxf(red[tid], red[tid + o]); __syncthreads(); }
    m = red[0];
    __syncthreads();
    float s = 0.f;
    #pragma unroll
    for (int j = 0; j < 4; j++) { v[j] = expf(v[j] - m); s += v[j]; }
    red[tid] = s; __syncthreads();
    for (int o = 64; o; o >>= 1) { if (tid < o) red[tid] += red[tid + o]; __syncthreads(); }
    float inv = 1.f / red[0];
    #pragma unroll
    for (int j = 0; j < 4; j++) row[tid + j*128] = v[j] * inv;
}

// ---------------------------------------------------------------------------
// Kernel 5: t partials: g_tp[sq][b,h,dim] over s in [sq*128, sq*128+128).
// grid (4 dchunks of 512, 16 b, 4 sq), block 256. Warp = 128 dims x 8 heads.
// x staged via cp.async double-buffered tiles of 8 tokens x 512 dims.
__global__ void __launch_bounds__(256, 3)
k_t(const float* __restrict__ x, const float* __restrict__ pos,
    const float* __restrict__ cls) {
    int b = blockIdx.y, sq = blockIdx.z;
    int tid = threadIdx.x, w = tid >> 5, lane = tid & 31;
    int dg = w >> 1;            // dim group 0..3 (128 dims each)
    int hh = (w & 1) * 8;       // head base
    int D0 = blockIdx.x * 512;  // CTA dim base
    int dim = D0 + dg*128 + lane*4;
    int sbase = sq * 128;
    __shared__ float ps[NH][128];      // 8 KB: this quarter's probs
    __shared__ float xs[2][8][512];    // 32 KB: x tiles (8 tokens x 512 dims)

    // Issue cp.async for stage st (8 tokens) into buffer buf. 1024 chunks; 4/thread.
    auto issue = [&](int st, int buf) {
        #pragma unroll
        for (int u = 0; u < 4; u++) {
            int k = tid + u * 256;
            int tt = k >> 7;           // token 0..7
            int c32 = k & 127;         // 16B chunk within 2KB row
            int d = D0 + c32*4;
            int c = d >> 8, r = d & 255;
            int s = sbase + st*8 + tt;
            const float* src = (s == 0)
                ? (cls + d)
                : (x + (size_t)b*XB + c*XC + (s-1)*HWSZ + r);
            cpa16(&xs[buf][tt][c32*4], src);
        }
        cpa_commit();
    };

    issue(0, 0);

    for (int t = tid; t < NH*128; t += 256) {
        int h = t >> 7, ss = t & 127;
        ps[h][ss] = g_sc[(b*NH + h)*SEQ + sbase + ss];
    }

    float4 acc[8];
    #pragma unroll
    for (int h = 0; h < 8; h++) acc[h] = make_float4(0.f, 0.f, 0.f, 0.f);

    const float* pp = pos + dim;

    for (int st = 0; st < 16; st++) {
        int buf = st & 1;
        if (st < 15) issue(st + 1, buf ^ 1);
        if (st < 15) cpa_wait1(); else cpa_wait0();
        __syncthreads();   // x tile (and on st=0, ps) visible
        #pragma unroll
        for (int k2 = 0; k2 < 2; k2++) {
            int sl = st*8 + k2*4;          // local s (0..127)
            int s  = sbase + sl;
            float4 tv[4];
            #pragma unroll
            for (int j = 0; j < 4; j++) {
                float4 xv = *reinterpret_cast<const float4*>(&xs[buf][k2*4 + j][dg*128 + lane*4]);
                float4 pv = *reinterpret_cast<const float4*>(&pp[(size_t)(s + j)*DIMN]);
                tv[j].x = xv.x + pv.x; tv[j].y = xv.y + pv.y;
                tv[j].z = xv.z + pv.z; tv[j].w = xv.w + pv.w;
            }
            #pragma unroll
            for (int h = 0; h < 8; h++) {
                float4 p4 = *reinterpret_cast<const float4*>(&ps[hh + h][sl]);
                acc[h].x += p4.x*tv[0].x + p4.y*tv[1].x + p4.z*tv[2].x + p4.w*tv[3].x;
                acc[h].y += p4.x*tv[0].y + p4.y*tv[1].y + p4.z*tv[2].y + p4.w*tv[3].y;
                acc[h].z += p4.x*tv[0].z + p4.y*tv[1].z + p4.z*tv[2].z + p4.w*tv[3].z;
                acc[h].w += p4.x*tv[0].w + p4.y*tv[1].w + p4.z*tv[2].w + p4.w*tv[3].w;
            }
        }
        __syncthreads();   // buffer reads done before re-issue
    }
    #pragma unroll
    for (int h = 0; h < 8; h++)
        *reinterpret_cast<float4*>(&g_tp[sq][(b*NH + hh + h)*DIMN + dim]) = acc[h];
}

// Kernel 5b: collapse the 4 s-partials (deterministic order).
// grid 512, block 256: 131072 threads x float4 = 524288 floats = BB*NH*DIMN.
__global__ void k_t_sum() {
    int i4 = blockIdx.x * 256 + threadIdx.x;   // float4 index, 131072 total
    float4 a = make_float4(0.f, 0.f, 0.f, 0.f);
    #pragma unroll
    for (int sq = 0; sq < 4; sq++) {
        float4 v = *reinterpret_cast<const float4*>(&g_tp[sq][i4*4]);
        a.x += v.x; a.y += v.y; a.z += v.z; a.w += v.w;
    }
    *reinterpret_cast<float4*>(&g_t[i4*4]) = a;
}

// ---------------------------------------------------------------------------
// Kernel 6a: partial ao over one d-chunk, 64 output cols per CTA.
// grid (2 jb, 16 h, 16 chd), block 256. smem 40 KB.
__global__ void k_avp(const float* __restrict__ qkvw) {
    int jb = blockIdx.x, h = blockIdx.y, chd = blockIdx.z;
    int tid = threadIdx.x;
    int lane = tid & 31, grp = tid >> 5;  // grp: b = grp and grp+8
    __shared__ float ts[16][128];
    __shared__ float ws[128][64];
    // stage t tile
    for (int t = tid; t < 2048; t += 256) {
        int bb = t >> 7, dd = t & 127;
        ts[bb][dd] = g_t[(bb*NH + h)*DIMN + chd*128 + dd];
    }
    // stage Wv tile (128 rows x 64 cols), float4
    const float* wsrc = qkvw + 2*DIMN + h*HD + jb*64;
    for (int t4 = tid; t4 < 2048; t4 += 256) {
        int dd = t4 >> 4, j4 = t4 & 15;
        *reinterpret_cast<float4*>(&ws[dd][j4*4]) =
            *reinterpret_cast<const float4*>(&wsrc[(chd*128 + dd)*QLD + j4*4]);
    }
    __syncthreads();
    float2 a0 = make_float2(0.f, 0.f), a1 = make_float2(0.f, 0.f);
    #pragma unroll 8
    for (int dd = 0; dd < 128; dd++) {
        float2 wv = *reinterpret_cast<const float2*>(&ws[dd][lane*2]);
        float t0 = ts[grp][dd], t1 = ts[grp + 8][dd];
        a0.x += t0*wv.x; a0.y += t0*wv.y;
        a1.x += t1*wv.x; a1.y += t1*wv.y;
    }
    int ocol = h*HD + jb*64 + lane*2;
    *reinterpret_cast<float2*>(&g_aop[chd][ grp     *DIMN + ocol]) = a0;
    *reinterpret_cast<float2*>(&g_aop[chd][(grp + 8)*DIMN + ocol]) = a1;
}

// Kernel 6b: reduce 16 chunk partials + bias -> g_ao. grid 128, block 256.
__global__ void k_ao_sum(const float* __restrict__ qkvb) {
    int idx = blockIdx.x * 256 + threadIdx.x;   // 0 .. 32767
    int col = idx & (DIMN-1);
    float a = qkvb[2*DIMN + col];
    #pragma unroll
    for (int c = 0; c < 16; c++) a += g_aop[c][idx];
    g_ao[idx] = a;
}

// ---------------------------------------------------------------------------
// Kernel 7a: partial proj over one d-chunk, 64 output cols per CTA.
// grid (32 eb, 16 chd), block 256. smem 40 KB.
__global__ void k_projp(const float* __restrict__ pw) {
    int eb = blockIdx.x, chd = blockIdx.y;
    int tid = threadIdx.x;
    int lane = tid & 31, grp = tid >> 5;
    __shared__ float as[16][128];
    __shared__ float ws[128][64];
    for (int t = tid; t < 2048; t += 256) {
        int bb = t >> 7, dd = t & 127;
        as[bb][dd] = g_ao[bb*DIMN + chd*128 + dd];
    }
    const float* wsrc = pw + eb*64;
    for (int t4 = tid; t4 < 2048; t4 += 256) {
        int dd = t4 >> 4, j4 = t4 & 15;
        *reinterpret_cast<float4*>(&ws[dd][j4*4]) =
            *reinterpret_cast<const float4*>(&wsrc[(chd*128 + dd)*DIMN + j4*4]);
    }
    __syncthreads();
    float2 a0 = make_float2(0.f, 0.f), a1 = make_float2(0.f, 0.f);
    #pragma unroll 8
    for (int dd = 0; dd < 128; dd++) {
        float2 wv = *reinterpret_cast<const float2*>(&ws[dd][lane*2]);
        float t0 = as[grp][dd], t1 = as[grp + 8][dd];
        a0.x += t0*wv.x; a0.y += t0*wv.y;
        a1.x += t1*wv.x; a1.y += t1*wv.y;
    }
    int e = eb*64 + lane*2;
    *reinterpret_cast<float2*>(&g_outp[chd][ grp     *DIMN + e]) = a0;
    *reinterpret_cast<float2*>(&g_outp[chd][(grp + 8)*DIMN + e]) = a1;
}

// Kernel 7b: reduce 16 chunk partials + bias -> out. grid 128, block 256.
__global__ void k_out_sum(const float* __restrict__ pb, float* __restrict__ out) {
    int idx = blockIdx.x * 256 + threadIdx.x;
    int e = idx & (DIMN-1);
    float a = pb[e];
    #pragma unroll
    for (int c = 0; c < 16; c++) a += g_outp[c][idx];
    out[idx] = a;
}

// ---------------------------------------------------------------------------
extern "C" void kernel_launch(void* const* d_in, const int* in_sizes, int n_in,
                              void* d_out, int out_size) {
    const float* x    = (const float*)d_in[0];
    const float* pos  = (const float*)d_in[1];
    const float* cls  = (const float*)d_in[2];
    const float* qkvw = (const float*)d_in[3];
    const float* qkvb = (const float*)d_in[4];
    const float* pw   = (const float*)d_in[5];
    const float* pb   = (const float*)d_in[6];
    float* out = (float*)d_out;

    k_q_part <<<dim3(16, 32), 128>>>(pos, cls, qkvw);
    k_q_sum  <<<16, 128>>>(qkvb);
    k_qhat   <<<dim3(256, 16), 256>>>(qkvw);
    k_scores <<<dim3(32, 16), 256>>>(x, pos, cls);
    k_softmax<<<256, 128>>>(qkvb);
    k_t      <<<dim3(4, 16, 4), 256>>>(x, pos, cls);
    k_t_sum  <<<512, 256>>>();
    k_avp    <<<dim3(2, 16, 16), 256>>>(qkvw);
    k_ao_sum <<<128, 256>>>(qkvb);
    k_projp  <<<dim3(32, 16), 256>>>(pw);
    k_out_sum<<<128, 256>>>(pb, out);
}

// round 13
// speedup vs baseline: 1.0141x; 1.0141x over previous
#include <cuda_runtime.h>
#include <cstdint>

// Problem constants
#define BB    16
#define CC    8
#define DD    511
#define DIMN  2048
#define SEQ   512
#define NH    16
#define HD    128
#define HWSZ  256
#define XB    (CC*DD*HWSZ)   // 1046528  (x batch stride)
#define XC    (DD*HWSZ)      // 130816   (x channel stride)
#define QLD   6144           // qkv_w leading dim (row length)
#define SCALE 0.08838834764831845f  // 128^-0.5

// Scratch (static device globals; no allocation anywhere)
__device__ float g_qp[32*DIMN];        // split-K partials for q
__device__ float g_q[DIMN];            // q for cls token (batch-independent)
__device__ float g_qhat[NH*DIMN];      // scale * Wk_h^T q_h
__device__ float g_sc[BB*NH*SEQ];      // scores -> probs (in place)
__device__ float g_tp[4][BB*NH*DIMN];  // s-split partials of t = P @ tok
__device__ float g_t[BB*NH*DIMN];      // t = P @ tok
__device__ float g_aop[16][BB*DIMN];   // d-chunk partials of attn out @ Wv
__device__ float g_ao[BB*DIMN];        // attention output (pre-proj)
__device__ float g_outp[16][BB*DIMN];  // d-chunk partials of final proj

// cp.async helpers (16B, bypass-L1 .cg path)
__device__ __forceinline__ void cpa16(void* smem_dst, const void* gsrc) {
    uint32_t sa = (uint32_t)__cvta_generic_to_shared(smem_dst);
    asm volatile("cp.async.cg.shared.global [%0], [%1], 16;" :: "r"(sa), "l"(gsrc));
}
__device__ __forceinline__ void cpa_commit() {
    asm volatile("cp.async.commit_group;");
}
__device__ __forceinline__ void cpa_wait1() {
    asm volatile("cp.async.wait_group 1;");
}

// ---------------------------------------------------------------------------
// Kernel 1a: split-K partial of q = tok0 @ Wq.
// grid (16 colblocks, 32 dchunks of 64 rows), block 128.
__global__ void k_q_part(const float* __restrict__ pos, const float* __restrict__ cls,
                         const float* __restrict__ qkvw) {
    __shared__ float t0[64];
    int dc = blockIdx.y;
    int tid = threadIdx.x;
    if (tid < 64) t0[tid] = cls[dc*64 + tid] + pos[dc*64 + tid];
    __syncthreads();
    int col = blockIdx.x * 128 + tid;
    const float* wp = qkvw + (dc*64)*QLD + col;
    float a0 = 0.f, a1 = 0.f, a2 = 0.f, a3 = 0.f;
    #pragma unroll 2
    for (int d = 0; d < 64; d += 8) {
        a0 += t0[d+0] * wp[(d+0)*QLD];
        a1 += t0[d+1] * wp[(d+1)*QLD];
        a2 += t0[d+2] * wp[(d+2)*QLD];
        a3 += t0[d+3] * wp[(d+3)*QLD];
        a0 += t0[d+4] * wp[(d+4)*QLD];
        a1 += t0[d+5] * wp[(d+5)*QLD];
        a2 += t0[d+6] * wp[(d+6)*QLD];
        a3 += t0[d+7] * wp[(d+7)*QLD];
    }
    g_qp[dc*DIMN + col] = (a0 + a1) + (a2 + a3);
}

// Kernel 1b: reduce the 32 partials (deterministic order) + bias. grid 16, block 128
__global__ void k_q_sum(const float* __restrict__ qkvb) {
    int col = blockIdx.x * 128 + threadIdx.x;
    float a = qkvb[col];
    #pragma unroll
    for (int dc = 0; dc < 32; dc++) a += g_qp[dc*DIMN + col];
    g_q[col] = a;
}

// ---------------------------------------------------------------------------
// Kernel 2: qhat[h, dim] = SCALE * sum_j qkv_w[dim, 2048 + h*128 + j] * q[h*128+j]
// grid (256, 16): 8 dims per CTA (one per warp), block 256, float4 loads.
__global__ void k_qhat(const float* __restrict__ qkvw) {
    int h = blockIdx.y;
    __shared__ float4 qv4[32];
    int tid = threadIdx.x;
    if (tid < 32) qv4[tid] = *reinterpret_cast<const float4*>(&g_q[h*HD + tid*4]);
    __syncthreads();
    int w = tid >> 5, lane = tid & 31;
    int dim = blockIdx.x * 8 + w;
    const float4* wr4 = reinterpret_cast<const float4*>(qkvw + dim*QLD + DIMN + h*HD);
    float4 wv = wr4[lane];
    float4 qv = qv4[lane];
    float p = wv.x*qv.x + wv.y*qv.y + wv.z*qv.z + wv.w*qv.w;
    #pragma unroll
    for (int o = 16; o; o >>= 1) p += __shfl_xor_sync(0xffffffffu, p, o);
    if (lane == 0) g_qhat[h*DIMN + dim] = p * SCALE;
}

// ---------------------------------------------------------------------------
// Kernel 3: scores[b,h,s] = qhat[h,:] . tok[b,s,:]  (tok built on the fly)
// grid (32 stiles, 16 b), block 256 (8 warps). Warp = 4 tokens x 8 heads.
// x staged via 3-buffer cp.async ring, ONE barrier per slice.
// smem: qh2 16 KB (256-dim chunks) + xs 24 KB = 40 KB.
__global__ void __launch_bounds__(256, 3)
k_scores(const float* __restrict__ x, const float* __restrict__ pos,
         const float* __restrict__ cls) {
    int b = blockIdx.y;
    int tid = threadIdx.x, w = tid >> 5, lane = tid & 31;
    int tg = w >> 1;            // token group 0..3
    int hh = (w & 1) * 8;       // head base: 0 or 8
    int s0c = blockIdx.x * 16;  // CTA token base
    int s0 = s0c + tg * 4;      // warp token base
    __shared__ float qh2[NH][256];     // 16 KB: current 256-dim chunk, all heads
    __shared__ float xs[3][16][128];   // 24 KB: x tile ring (16 tokens x 128 dims)

    // Issue cp.async for slice ci into buffer buf. 512 16B-chunks; 2 per thread.
    auto issue = [&](int ci, int buf) {
        int dn = ci * 128;
        int cn = dn >> 8, rn = dn & 255;
        #pragma unroll
        for (int u = 0; u < 2; u++) {
            int k = tid + u * 256;
            int tt = k >> 5;           // token 0..15
            int c16 = k & 31;          // 16B chunk within 512B row
            int s = s0c + tt;
            const float* src = (s == 0)
                ? (cls + dn + c16*4)
                : (x + (size_t)b*XB + cn*XC + (s-1)*HWSZ + rn + c16*4);
            cpa16(&xs[buf][tt][c16*4], src);
        }
        cpa_commit();
    };

    float acc[8][4];
    #pragma unroll
    for (int h = 0; h < 8; h++)
        #pragma unroll
        for (int j = 0; j < 4; j++) acc[h][j] = 0.f;

    issue(0, 0);
    issue(1, 1);

    for (int ci = 0; ci < 16; ci++) {
        cpa_wait1();           // group ci complete (group ci+1 may be in flight)
        __syncthreads();       // tile ci visible to all; all done with slice ci-1
        // re-issue: buffer (ci+2)%3 was last read at slice ci-1 -> safe now
        int nx = (ci + 2 < 16) ? ci + 2 : 15;   // clamp keeps group count uniform
        issue(nx, (ci + 2) % 3);
        if ((ci & 1) == 0) {   // reload qh chunk (old chunk last read slice ci-1)
            int qc = ci >> 1;
            #pragma unroll
            for (int t4 = tid; t4 < NH*64; t4 += 256) {
                int h = t4 >> 6, dd4 = t4 & 63;
                *reinterpret_cast<float4*>(&qh2[h][dd4*4]) =
                    *reinterpret_cast<const float4*>(&g_qhat[h*DIMN + qc*256 + dd4*4]);
            }
            __syncthreads();
        }
        // compute slice ci
        int buf = ci % 3;
        int ddc = (ci & 1)*128 + lane*4;   // dim within current 256-chunk
        int d   = ci*128 + lane*4;         // absolute dim
        float4 tv[4];
        #pragma unroll
        for (int j = 0; j < 4; j++) {
            float4 xv = *reinterpret_cast<const float4*>(&xs[buf][tg*4 + j][lane*4]);
            float4 pv = *reinterpret_cast<const float4*>(&pos[(s0 + j)*DIMN + d]);
            tv[j].x = xv.x + pv.x; tv[j].y = xv.y + pv.y;
            tv[j].z = xv.z + pv.z; tv[j].w = xv.w + pv.w;
        }
        #pragma unroll
        for (int h = 0; h < 8; h++) {
            float4 qv = *reinterpret_cast<const float4*>(&qh2[hh + h][ddc]);
            #pragma unroll
            for (int j = 0; j < 4; j++) {
                acc[h][j] += qv.x*tv[j].x + qv.y*tv[j].y
                           + qv.z*tv[j].z + qv.w*tv[j].w;
            }
        }
    }
    // butterfly reduce (32 outputs per warp)
    #pragma unroll
    for (int o = 16; o; o >>= 1)
        #pragma unroll
        for (int h = 0; h < 8; h++)
            #pragma unroll
            for (int j = 0; j < 4; j++)
                acc[h][j] += __shfl_xor_sync(0xffffffffu, acc[h][j], o);
    float outv = 0.f;
    #pragma unroll
    for (int h = 0; h < 8; h++)
        #pragma unroll
        for (int j = 0; j < 4; j++)
            if (lane == h*4 + j) outv = acc[h][j];
    int h8 = lane >> 2, j = lane & 3;
    g_sc[(b*NH + hh + h8)*SEQ + s0c + tg*4 + j] = outv;
}

// ---------------------------------------------------------------------------
// Kernel 4: softmax over s (512) per (b,h) row; adds the q.bk bias term.
// grid 256, block 128
__global__ void k_softmax(const float* __restrict__ qkvb) {
    int bh = blockIdx.x;
    int h = bh & 15;
    int tid = threadIdx.x;
    __shared__ float red[128];

    red[tid] = g_q[h*HD + tid] * qkvb[DIMN + h*HD + tid];
    __syncthreads();
    for (int o = 64; o; o >>= 1) { if (tid < o) red[tid] += red[tid + o]; __syncthreads(); }
    float sbias = red[0] * SCALE;
    __syncthreads();

    float* row = g_sc + bh*SEQ;
    float v[4];
    float m = -1e30f;
    #pragma unroll
    for (int j = 0; j < 4; j++) { v[j] = row[tid + j*128] + sbias; m = fmaxf(m, v[j]); }
    red[tid] = m; __syncthreads();
    for (int o = 64; o; o >>= 1) { if (tid < o) red[tid] = fmaxf(red[tid], red[tid + o]); __syncthreads(); }
    m = red[0];
    __syncthreads();
    float s = 0.f;
    #pragma unroll
    for (int j = 0; j < 4; j++) { v[j] = expf(v[j] - m); s += v[j]; }
    red[tid] = s; __syncthreads();
    for (int o = 64; o; o >>= 1) { if (tid < o) red[tid] += red[tid + o]; __syncthreads(); }
    float inv = 1.f / red[0];
    #pragma unroll
    for (int j = 0; j < 4; j++) row[tid + j*128] = v[j] * inv;
}

// ---------------------------------------------------------------------------
// Kernel 5: t partials: g_tp[sq][b,h,dim] over s in [sq*128, sq*128+128).
// grid (4 dchunks of 512, 16 b, 4 sq), block 256. Warp = 128 dims x 8 heads.
// x staged via 3-buffer cp.async ring (4 tokens x 512 dims per stage), 32 stages.
// smem: ps 8 KB + xs 24 KB = 32 KB.
__global__ void __launch_bounds__(256, 3)
k_t(const float* __restrict__ x, const float* __restrict__ pos,
    const float* __restrict__ cls) {
    int b = blockIdx.y, sq = blockIdx.z;
    int tid = threadIdx.x, w = tid >> 5, lane = tid & 31;
    int dg = w >> 1;            // dim group 0..3 (128 dims each)
    int hh = (w & 1) * 8;       // head base
    int D0 = blockIdx.x * 512;  // CTA dim base
    int dim = D0 + dg*128 + lane*4;
    int sbase = sq * 128;
    __shared__ float ps[NH][128];      // 8 KB: this quarter's probs
    __shared__ float xs[3][4][512];    // 24 KB: x tile ring (4 tokens x 512 dims)

    // Issue cp.async for stage st (4 tokens) into buffer buf. 512 chunks; 2/thread.
    auto issue = [&](int st, int buf) {
        #pragma unroll
        for (int u = 0; u < 2; u++) {
            int k = tid + u * 256;
            int tt = k >> 7;           // token 0..3
            int c32 = k & 127;         // 16B chunk within 2KB row
            int d = D0 + c32*4;
            int c = d >> 8, r = d & 255;
            int s = sbase + st*4 + tt;
            const float* src = (s == 0)
                ? (cls + d)
                : (x + (size_t)b*XB + c*XC + (s-1)*HWSZ + r);
            cpa16(&xs[buf][tt][c32*4], src);
        }
        cpa_commit();
    };

    issue(0, 0);
    issue(1, 1);

    for (int t = tid; t < NH*128; t += 256) {
        int h = t >> 7, ss = t & 127;
        ps[h][ss] = g_sc[(b*NH + h)*SEQ + sbase + ss];
    }

    float4 acc[8];
    #pragma unroll
    for (int h = 0; h < 8; h++) acc[h] = make_float4(0.f, 0.f, 0.f, 0.f);

    const float* pp = pos + dim;

    for (int st = 0; st < 32; st++) {
        cpa_wait1();           // stage st complete
        __syncthreads();       // tile (and on st=0, ps) visible; stage st-1 done
        int nx = (st + 2 < 32) ? st + 2 : 31;
        issue(nx, (st + 2) % 3);
        int buf = st % 3;
        int sl = st*4;                 // local s (0..127)
        int s  = sbase + sl;
        float4 tv[4];
        #pragma unroll
        for (int j = 0; j < 4; j++) {
            float4 xv = *reinterpret_cast<const float4*>(&xs[buf][j][dg*128 + lane*4]);
            float4 pv = *reinterpret_cast<const float4*>(&pp[(size_t)(s + j)*DIMN]);
            tv[j].x = xv.x + pv.x; tv[j].y = xv.y + pv.y;
            tv[j].z = xv.z + pv.z; tv[j].w = xv.w + pv.w;
        }
        #pragma unroll
        for (int h = 0; h < 8; h++) {
            float4 p4 = *reinterpret_cast<const float4*>(&ps[hh + h][sl]);
            acc[h].x += p4.x*tv[0].x + p4.y*tv[1].x + p4.z*tv[2].x + p4.w*tv[3].x;
            acc[h].y += p4.x*tv[0].y + p4.y*tv[1].y + p4.z*tv[2].y + p4.w*tv[3].y;
            acc[h].z += p4.x*tv[0].z + p4.y*tv[1].z + p4.z*tv[2].z + p4.w*tv[3].z;
            acc[h].w += p4.x*tv[0].w + p4.y*tv[1].w + p4.z*tv[2].w + p4.w*tv[3].w;
        }
    }
    #pragma unroll
    for (int h = 0; h < 8; h++)
        *reinterpret_cast<float4*>(&g_tp[sq][(b*NH + hh + h)*DIMN + dim]) = acc[h];
}

// Kernel 5b: collapse the 4 s-partials (deterministic order).
// grid 512, block 256: 131072 threads x float4 = 524288 floats = BB*NH*DIMN.
__global__ void k_t_sum() {
    int i4 = blockIdx.x * 256 + threadIdx.x;   // float4 index, 131072 total
    float4 a = make_float4(0.f, 0.f, 0.f, 0.f);
    #pragma unroll
    for (int sq = 0; sq < 4; sq++) {
        float4 v = *reinterpret_cast<const float4*>(&g_tp[sq][i4*4]);
        a.x += v.x; a.y += v.y; a.z += v.z; a.w += v.w;
    }
    *reinterpret_cast<float4*>(&g_t[i4*4]) = a;
}

// ---------------------------------------------------------------------------
// Kernel 6a: partial ao over one d-chunk, 64 output cols per CTA.
// grid (2 jb, 16 h, 16 chd), block 256. smem 40 KB.
__global__ void k_avp(const float* __restrict__ qkvw) {
    int jb = blockIdx.x, h = blockIdx.y, chd = blockIdx.z;
    int tid = threadIdx.x;
    int lane = tid & 31, grp = tid >> 5;  // grp: b = grp and grp+8
    __shared__ float ts[16][128];
    __shared__ float ws[128][64];
    // stage t tile
    for (int t = tid; t < 2048; t += 256) {
        int bb = t >> 7, dd = t & 127;
        ts[bb][dd] = g_t[(bb*NH + h)*DIMN + chd*128 + dd];
    }
    // stage Wv tile (128 rows x 64 cols), float4
    const float* wsrc = qkvw + 2*DIMN + h*HD + jb*64;
    for (int t4 = tid; t4 < 2048; t4 += 256) {
        int dd = t4 >> 4, j4 = t4 & 15;
        *reinterpret_cast<float4*>(&ws[dd][j4*4]) =
            *reinterpret_cast<const float4*>(&wsrc[(chd*128 + dd)*QLD + j4*4]);
    }
    __syncthreads();
    float2 a0 = make_float2(0.f, 0.f), a1 = make_float2(0.f, 0.f);
    #pragma unroll 8
    for (int dd = 0; dd < 128; dd++) {
        float2 wv = *reinterpret_cast<const float2*>(&ws[dd][lane*2]);
        float t0 = ts[grp][dd], t1 = ts[grp + 8][dd];
        a0.x += t0*wv.x; a0.y += t0*wv.y;
        a1.x += t1*wv.x; a1.y += t1*wv.y;
    }
    int ocol = h*HD + jb*64 + lane*2;
    *reinterpret_cast<float2*>(&g_aop[chd][ grp     *DIMN + ocol]) = a0;
    *reinterpret_cast<float2*>(&g_aop[chd][(grp + 8)*DIMN + ocol]) = a1;
}

// Kernel 6b: reduce 16 chunk partials + bias -> g_ao. grid 128, block 256.
__global__ void k_ao_sum(const float* __restrict__ qkvb) {
    int idx = blockIdx.x * 256 + threadIdx.x;   // 0 .. 32767
    int col = idx & (DIMN-1);
    float a = qkvb[2*DIMN + col];
    #pragma unroll
    for (int c = 0; c < 16; c++) a += g_aop[c][idx];
    g_ao[idx] = a;
}

// ---------------------------------------------------------------------------
// Kernel 7a: partial proj over one d-chunk, 64 output cols per CTA.
// grid (32 eb, 16 chd), block 256. smem 40 KB.
__global__ void k_projp(const float* __restrict__ pw) {
    int eb = blockIdx.x, chd = blockIdx.y;
    int tid = threadIdx.x;
    int lane = tid & 31, grp = tid >> 5;
    __shared__ float as[16][128];
    __shared__ float ws[128][64];
    for (int t = tid; t < 2048; t += 256) {
        int bb = t >> 7, dd = t & 127;
        as[bb][dd] = g_ao[bb*DIMN + chd*128 + dd];
    }
    const float* wsrc = pw + eb*64;
    for (int t4 = tid; t4 < 2048; t4 += 256) {
        int dd = t4 >> 4, j4 = t4 & 15;
        *reinterpret_cast<float4*>(&ws[dd][j4*4]) =
            *reinterpret_cast<const float4*>(&wsrc[(chd*128 + dd)*DIMN + j4*4]);
    }
    __syncthreads();
    float2 a0 = make_float2(0.f, 0.f), a1 = make_float2(0.f, 0.f);
    #pragma unroll 8
    for (int dd = 0; dd < 128; dd++) {
        float2 wv = *reinterpret_cast<const float2*>(&ws[dd][lane*2]);
        float t0 = as[grp][dd], t1 = as[grp + 8][dd];
        a0.x += t0*wv.x; a0.y += t0*wv.y;
        a1.x += t1*wv.x; a1.y += t1*wv.y;
    }
    int e = eb*64 + lane*2;
    *reinterpret_cast<float2*>(&g_outp[chd][ grp     *DIMN + e]) = a0;
    *reinterpret_cast<float2*>(&g_outp[chd][(grp + 8)*DIMN + e]) = a1;
}

// Kernel 7b: reduce 16 chunk partials + bias -> out. grid 128, block 256.
__global__ void k_out_sum(const float* __restrict__ pb, float* __restrict__ out) {
    int idx = blockIdx.x * 256 + threadIdx.x;
    int e = idx & (DIMN-1);
    float a = pb[e];
    #pragma unroll
    for (int c = 0; c < 16; c++) a += g_outp[c][idx];
    out[idx] = a;
}

// ---------------------------------------------------------------------------
extern "C" void kernel_launch(void* const* d_in, const int* in_sizes, int n_in,
                              void* d_out, int out_size) {
    const float* x    = (const float*)d_in[0];
    const float* pos  = (const float*)d_in[1];
    const float* cls  = (const float*)d_in[2];
    const float* qkvw = (const float*)d_in[3];
    const float* qkvb = (const float*)d_in[4];
    const float* pw   = (const float*)d_in[5];
    const float* pb   = (const float*)d_in[6];
    float* out = (float*)d_out;

    k_q_part <<<dim3(16, 32), 128>>>(pos, cls, qkvw);
    k_q_sum  <<<16, 128>>>(qkvb);
    k_qhat   <<<dim3(256, 16), 256>>>(qkvw);
    k_scores <<<dim3(32, 16), 256>>>(x, pos, cls);
    k_softmax<<<256, 128>>>(qkvb);
    k_t      <<<dim3(4, 16, 4), 256>>>(x, pos, cls);
    k_t_sum  <<<512, 256>>>();
    k_avp    <<<dim3(2, 16, 16), 256>>>(qkvw);
    k_ao_sum <<<128, 256>>>(qkvb);
    k_projp  <<<dim3(32, 16), 256>>>(pw);
    k_out_sum<<<128, 256>>>(pb, out);
}

// round 14
// speedup vs baseline: 1.0539x; 1.0393x over previous
#include <cuda_runtime.h>
#include <cstdint>

// Problem constants
#define BB    16
#define CC    8
#define DD    511
#define DIMN  2048
#define SEQ   512
#define NH    16
#define HD    128
#define HWSZ  256
#define XB    (CC*DD*HWSZ)   // 1046528  (x batch stride)
#define XC    (DD*HWSZ)      // 130816   (x channel stride)
#define QLD   6144           // qkv_w leading dim (row length)
#define SCALE 0.08838834764831845f  // 128^-0.5

// Scratch (static device globals; no allocation anywhere)
__device__ float g_qp[32*DIMN];        // split-K partials for q
__device__ float g_q[DIMN];            // q for cls token (batch-independent)
__device__ float g_qhat[NH*DIMN];      // scale * Wk_h^T q_h
__device__ float g_sposp[8][NH*SEQ];   // d-split partials of qhat.(pos+cls0)
__device__ float g_sc[BB*NH*SEQ];      // scores (x part) -> probs (in place)
__device__ float g_tp[4][BB*NH*DIMN];  // s-split partials of t = P @ tok
__device__ float g_aop[16][BB*DIMN];   // d-chunk partials of attn out @ Wv
__device__ float g_ao[BB*DIMN];        // attention output (pre-proj)
__device__ float g_outp[16][BB*DIMN];  // d-chunk partials of final proj

// ---------------------------------------------------------------------------
// Kernel 1a: split-K partial of q = tok0 @ Wq.
// grid (16 colblocks, 32 dchunks of 64 rows), block 128.
__global__ void k_q_part(const float* __restrict__ pos, const float* __restrict__ cls,
                         const float* __restrict__ qkvw) {
    __shared__ float t0[64];
    int dc = blockIdx.y;
    int tid = threadIdx.x;
    if (tid < 64) t0[tid] = cls[dc*64 + tid] + pos[dc*64 + tid];
    __syncthreads();
    int col = blockIdx.x * 128 + tid;
    const float* wp = qkvw + (dc*64)*QLD + col;
    float a0 = 0.f, a1 = 0.f, a2 = 0.f, a3 = 0.f;
    #pragma unroll 2
    for (int d = 0; d < 64; d += 8) {
        a0 += t0[d+0] * wp[(d+0)*QLD];
        a1 += t0[d+1] * wp[(d+1)*QLD];
        a2 += t0[d+2] * wp[(d+2)*QLD];
        a3 += t0[d+3] * wp[(d+3)*QLD];
        a0 += t0[d+4] * wp[(d+4)*QLD];
        a1 += t0[d+5] * wp[(d+5)*QLD];
        a2 += t0[d+6] * wp[(d+6)*QLD];
        a3 += t0[d+7] * wp[(d+7)*QLD];
    }
    g_qp[dc*DIMN + col] = (a0 + a1) + (a2 + a3);
}

// Kernel 1b: reduce the 32 partials (deterministic order) + bias. grid 16, block 128
__global__ void k_q_sum(const float* __restrict__ qkvb) {
    int col = blockIdx.x * 128 + threadIdx.x;
    float a = qkvb[col];
    #pragma unroll
    for (int dc = 0; dc < 32; dc++) a += g_qp[dc*DIMN + col];
    g_q[col] = a;
}

// ---------------------------------------------------------------------------
// Kernel 2: qhat[h, dim] = SCALE * sum_j qkv_w[dim, 2048 + h*128 + j] * q[h*128+j]
// grid (256, 16): 8 dims per CTA (one per warp), block 256, float4 loads.
__global__ void k_qhat(const float* __restrict__ qkvw) {
    int h = blockIdx.y;
    __shared__ float4 qv4[32];
    int tid = threadIdx.x;
    if (tid < 32) qv4[tid] = *reinterpret_cast<const float4*>(&g_q[h*HD + tid*4]);
    __syncthreads();
    int w = tid >> 5, lane = tid & 31;
    int dim = blockIdx.x * 8 + w;
    const float4* wr4 = reinterpret_cast<const float4*>(qkvw + dim*QLD + DIMN + h*HD);
    float4 wv = wr4[lane];
    float4 qv = qv4[lane];
    float p = wv.x*qv.x + wv.y*qv.y + wv.z*qv.z + wv.w*qv.w;
    #pragma unroll
    for (int o = 16; o; o >>= 1) p += __shfl_xor_sync(0xffffffffu, p, o);
    if (lane == 0) g_qhat[h*DIMN + dim] = p * SCALE;
}

// ---------------------------------------------------------------------------
// Kernel 2b: spos partials: g_sposp[ds][h,s] = qhat[h, ds*256:+256] . (pos[s] + [s==0]cls)
// grid (32 stiles, 8 dsplits), block 256 (8 warps). Warp = 4 tokens x 8 heads.
__global__ void k_spos(const float* __restrict__ pos, const float* __restrict__ cls) {
    int ds = blockIdx.y;
    int b0 = ds * 256;          // dim base
    int tid = threadIdx.x, w = tid >> 5, lane = tid & 31;
    int tg = w >> 1;
    int hh = (w & 1) * 8;
    int s0 = blockIdx.x * 16 + tg * 4;
    __shared__ float qh[NH][256];   // 16 KB

    for (int t4 = tid; t4 < NH*64; t4 += 256) {
        int h = t4 >> 6, dd4 = t4 & 63;
        *reinterpret_cast<float4*>(&qh[h][dd4*4]) =
            *reinterpret_cast<const float4*>(&g_qhat[h*DIMN + b0 + dd4*4]);
    }
    __syncthreads();

    float acc[8][4];
    #pragma unroll
    for (int h = 0; h < 8; h++)
        #pragma unroll
        for (int j = 0; j < 4; j++) acc[h][j] = 0.f;

    #pragma unroll
    for (int it = 0; it < 2; it++) {
        int dd = it*128 + lane*4;
        int d  = b0 + dd;
        float4 tv[4];
        #pragma unroll
        for (int j = 0; j < 4; j++) {
            int s = s0 + j;
            float4 pv = *reinterpret_cast<const float4*>(&pos[s*DIMN + d]);
            if (s == 0) {
                float4 cv = *reinterpret_cast<const float4*>(&cls[d]);
                pv.x += cv.x; pv.y += cv.y; pv.z += cv.z; pv.w += cv.w;
            }
            tv[j] = pv;
        }
        #pragma unroll
        for (int h = 0; h < 8; h++) {
            float4 qv = *reinterpret_cast<const float4*>(&qh[hh + h][dd]);
            #pragma unroll
            for (int j = 0; j < 4; j++)
                acc[h][j] += qv.x*tv[j].x + qv.y*tv[j].y + qv.z*tv[j].z + qv.w*tv[j].w;
        }
    }
    #pragma unroll
    for (int o = 16; o; o >>= 1)
        #pragma unroll
        for (int h = 0; h < 8; h++)
            #pragma unroll
            for (int j = 0; j < 4; j++)
                acc[h][j] += __shfl_xor_sync(0xffffffffu, acc[h][j], o);
    float outv = 0.f;
    #pragma unroll
    for (int h = 0; h < 8; h++)
        #pragma unroll
        for (int j = 0; j < 4; j++)
            if (lane == h*4 + j) outv = acc[h][j];
    int h8 = lane >> 2, j = lane & 3;
    g_sposp[ds][(hh + h8)*SEQ + s0 + j] = outv;
}

// ---------------------------------------------------------------------------
// Kernel 3: scores_x[b,h,s] = qhat[h,:] . x-part of tok[b,s,:]  (s=0 -> 0)
// grid (32 stiles, 16 b), block 256 (8 warps). Warp = 4 tokens x 8 heads.
// Lane owns 4 consecutive dims (float4). Double-buffered x prefetch. NO pos.
__global__ void k_scores(const float* __restrict__ x) {
    int b = blockIdx.y;
    int tid = threadIdx.x, w = tid >> 5, lane = tid & 31;
    int tg = w >> 1;            // token group 0..3
    int hh = (w & 1) * 8;       // head base: 0 or 8
    int s0 = blockIdx.x * 16 + tg * 4;
    __shared__ float qh[NH * 512];   // 32 KB, current 512-dim chunk, all heads

    const float4 z4 = make_float4(0.f, 0.f, 0.f, 0.f);

    float acc[8][4];
    #pragma unroll
    for (int h = 0; h < 8; h++)
        #pragma unroll
        for (int j = 0; j < 4; j++) acc[h][j] = 0.f;

    float4 xva[4], xvb[4];
    // prefetch x for slice 0
    {
        int d = lane*4;
        int c = d >> 8, r = d & 255;
        #pragma unroll
        for (int j = 0; j < 4; j++) {
            int s = s0 + j;
            xva[j] = (s == 0) ? z4
                   : *reinterpret_cast<const float4*>(&x[(size_t)b*XB + c*XC + (s-1)*HWSZ + r]);
        }
    }

    for (int ch = 0; ch < 4; ch++) {
        __syncthreads();
        // stage qhat chunk (float4)
        for (int t4 = tid; t4 < NH*128; t4 += 256) {
            int h = t4 >> 7, dd4 = t4 & 127;
            *reinterpret_cast<float4*>(&qh[h*512 + dd4*4]) =
                *reinterpret_cast<const float4*>(&g_qhat[h*DIMN + ch*512 + dd4*4]);
        }
        __syncthreads();
        #pragma unroll
        for (int it = 0; it < 4; it++) {
            int ci = ch*4 + it;                 // global slice 0..15
            float4* cur = (it & 1) ? xvb : xva; // parity static in it
            float4* nxt = (it & 1) ? xva : xvb;
            // prefetch next slice's x
            if (ci < 15) {
                int dn = (ci+1)*128 + lane*4;
                int cn = dn >> 8, rn = dn & 255;
                #pragma unroll
                for (int j = 0; j < 4; j++) {
                    int s = s0 + j;
                    nxt[j] = (s == 0) ? z4
                           : *reinterpret_cast<const float4*>(&x[(size_t)b*XB + cn*XC + (s-1)*HWSZ + rn]);
                }
            }
            // compute current slice (pure qv . xv)
            int dd = it*128 + lane*4;           // dim within current 512-chunk
            #pragma unroll
            for (int h = 0; h < 8; h++) {
                float4 qv = *reinterpret_cast<const float4*>(&qh[(hh + h)*512 + dd]);
                #pragma unroll
                for (int j = 0; j < 4; j++) {
                    acc[h][j] += qv.x*cur[j].x + qv.y*cur[j].y
                               + qv.z*cur[j].z + qv.w*cur[j].w;
                }
            }
        }
    }
    // butterfly reduce (32 outputs per warp)
    #pragma unroll
    for (int o = 16; o; o >>= 1)
        #pragma unroll
        for (int h = 0; h < 8; h++)
            #pragma unroll
            for (int j = 0; j < 4; j++)
                acc[h][j] += __shfl_xor_sync(0xffffffffu, acc[h][j], o);
    float outv = 0.f;
    #pragma unroll
    for (int h = 0; h < 8; h++)
        #pragma unroll
        for (int j = 0; j < 4; j++)
            if (lane == h*4 + j) outv = acc[h][j];
    int h8 = lane >> 2, j = lane & 3;
    g_sc[(b*NH + hh + h8)*SEQ + s0 + j] = outv;
}

// ---------------------------------------------------------------------------
// Kernel 4: softmax over s (512) per (b,h) row; adds q.bk bias + spos terms.
// grid 256, block 128
__global__ void k_softmax(const float* __restrict__ qkvb) {
    int bh = blockIdx.x;
    int h = bh & 15;
    int tid = threadIdx.x;
    __shared__ float red[128];

    red[tid] = g_q[h*HD + tid] * qkvb[DIMN + h*HD + tid];
    __syncthreads();
    for (int o = 64; o; o >>= 1) { if (tid < o) red[tid] += red[tid + o]; __syncthreads(); }
    float sbias = red[0] * SCALE;
    __syncthreads();

    float* row = g_sc + bh*SEQ;
    float v[4];
    // spos = sum of the 8 d-split partials (deterministic order)
    #pragma unroll
    for (int j = 0; j < 4; j++) {
        float sp = sbias;
        #pragma unroll
        for (int k = 0; k < 8; k++) sp += g_sposp[k][h*SEQ + tid + j*128];
        v[j] = row[tid + j*128] + sp;
    }
    float m = -1e30f;
    #pragma unroll
    for (int j = 0; j < 4; j++) m = fmaxf(m, v[j]);
    red[tid] = m; __syncthreads();
    for (int o = 64; o; o >>= 1) { if (tid < o) red[tid] = fmaxf(red[tid], red[tid + o]); __syncthreads(); }
    m = red[0];
    __syncthreads();
    float s = 0.f;
    #pragma unroll
    for (int j = 0; j < 4; j++) { v[j] = expf(v[j] - m); s += v[j]; }
    red[tid] = s; __syncthreads();
    for (int o = 64; o; o >>= 1) { if (tid < o) red[tid] += red[tid + o]; __syncthreads(); }
    float inv = 1.f / red[0];
    #pragma unroll
    for (int j = 0; j < 4; j++) row[tid + j*128] = v[j] * inv;
}

// ---------------------------------------------------------------------------
// Kernel 5: t partials: g_tp[sq][b,h,dim] over s in [sq*128, sq*128+128).
// grid (4 dchunks, 16 b, 4 sq), block 256. Warp = 128 dims x 8 heads; lane = 4 dims.
// Double-buffered x prefetch (R11 proven form).
__global__ void k_t(const float* __restrict__ x, const float* __restrict__ pos,
                    const float* __restrict__ cls) {
    int b = blockIdx.y, sq = blockIdx.z;
    int tid = threadIdx.x, w = tid >> 5, lane = tid & 31;
    int dg = w >> 1;            // dim group 0..3
    int hh = (w & 1) * 8;       // head base
    int dim = blockIdx.x*512 + dg*128 + lane*4;
    int sbase = sq * 128;
    __shared__ float ps[NH][128];  // 8 KB: this quarter's probs
    for (int t = tid; t < NH*128; t += 256) {
        int h = t >> 7, ss = t & 127;
        ps[h][ss] = g_sc[(b*NH + h)*SEQ + sbase + ss];
    }
    __syncthreads();

    int c = dim >> 8, r = dim & 255;          // 4 dims share channel c
    const float* xp = x + (size_t)b*XB + c*XC + r;   // token s>=1 -> xp + (s-1)*HWSZ
    const float* pp = pos + dim;

    float4 acc[8];
    #pragma unroll
    for (int h = 0; h < 8; h++) acc[h] = make_float4(0.f, 0.f, 0.f, 0.f);

    float4 xa[4], xb[4];
    // preload k=0 tokens (s = sbase..sbase+3; s==0 only when sq==0)
    #pragma unroll
    for (int j = 0; j < 4; j++) {
        int s = sbase + j;
        xa[j] = (s == 0) ? *reinterpret_cast<const float4*>(&cls[dim])
                         : *reinterpret_cast<const float4*>(&xp[(s-1)*HWSZ]);
    }

    #pragma unroll 4
    for (int k2 = 0; k2 < 16; k2++) {
        int k = k2*2;
        // prefetch k+1 (s >= 1 always)
        {
            int s = sbase + (k+1)*4;
            #pragma unroll
            for (int j = 0; j < 4; j++)
                xb[j] = *reinterpret_cast<const float4*>(&xp[(s + j - 1)*HWSZ]);
        }
        // compute k from xa
        {
            int s = sbase + k*4;
            float4 tv[4];
            #pragma unroll
            for (int j = 0; j < 4; j++) {
                float4 pv = *reinterpret_cast<const float4*>(&pp[(size_t)(s + j)*DIMN]);
                tv[j].x = xa[j].x+pv.x; tv[j].y = xa[j].y+pv.y;
                tv[j].z = xa[j].z+pv.z; tv[j].w = xa[j].w+pv.w;
            }
            #pragma unroll
            for (int h = 0; h < 8; h++) {
                float4 p4 = *reinterpret_cast<const float4*>(&ps[hh + h][k*4]);
                acc[h].x += p4.x*tv[0].x + p4.y*tv[1].x + p4.z*tv[2].x + p4.w*tv[3].x;
                acc[h].y += p4.x*tv[0].y + p4.y*tv[1].y + p4.z*tv[2].y + p4.w*tv[3].y;
                acc[h].z += p4.x*tv[0].z + p4.y*tv[1].z + p4.z*tv[2].z + p4.w*tv[3].z;
                acc[h].w += p4.x*tv[0].w + p4.y*tv[1].w + p4.z*tv[2].w + p4.w*tv[3].w;
            }
        }
        // prefetch k+2 into xa
        if (k2 < 15) {
            int s = sbase + (k+2)*4;
            #pragma unroll
            for (int j = 0; j < 4; j++)
                xa[j] = *reinterpret_cast<const float4*>(&xp[(s + j - 1)*HWSZ]);
        }
        // compute k+1 from xb
        {
            int s = sbase + (k+1)*4;
            float4 tv[4];
            #pragma unroll
            for (int j = 0; j < 4; j++) {
                float4 pv = *reinterpret_cast<const float4*>(&pp[(size_t)(s + j)*DIMN]);
                tv[j].x = xb[j].x+pv.x; tv[j].y = xb[j].y+pv.y;
                tv[j].z = xb[j].z+pv.z; tv[j].w = xb[j].w+pv.w;
            }
            #pragma unroll
            for (int h = 0; h < 8; h++) {
                float4 p4 = *reinterpret_cast<const float4*>(&ps[hh + h][(k+1)*4]);
                acc[h].x += p4.x*tv[0].x + p4.y*tv[1].x + p4.z*tv[2].x + p4.w*tv[3].x;
                acc[h].y += p4.x*tv[0].y + p4.y*tv[1].y + p4.z*tv[2].y + p4.w*tv[3].y;
                acc[h].z += p4.x*tv[0].z + p4.y*tv[1].z + p4.z*tv[2].z + p4.w*tv[3].z;
                acc[h].w += p4.x*tv[0].w + p4.y*tv[1].w + p4.z*tv[2].w + p4.w*tv[3].w;
            }
        }
    }
    #pragma unroll
    for (int h = 0; h < 8; h++)
        *reinterpret_cast<float4*>(&g_tp[sq][(b*NH + hh + h)*DIMN + dim]) = acc[h];
}

// ---------------------------------------------------------------------------
// Kernel 6a: partial ao over one d-chunk, 64 output cols per CTA.
// Sums the 4 s-partials of t while staging (replaces k_t_sum).
// grid (2 jb, 16 h, 16 chd), block 256. smem 40 KB.
__global__ void k_avp(const float* __restrict__ qkvw) {
    int jb = blockIdx.x, h = blockIdx.y, chd = blockIdx.z;
    int tid = threadIdx.x;
    int lane = tid & 31, grp = tid >> 5;  // grp: b = grp and grp+8
    __shared__ float ts[16][128];
    __shared__ float ws[128][64];
    // stage t tile, summing s-partials (deterministic order)
    for (int t = tid; t < 2048; t += 256) {
        int bb = t >> 7, dd = t & 127;
        int idx = (bb*NH + h)*DIMN + chd*128 + dd;
        ts[bb][dd] = (g_tp[0][idx] + g_tp[1][idx]) + (g_tp[2][idx] + g_tp[3][idx]);
    }
    // stage Wv tile (128 rows x 64 cols), float4
    const float* wsrc = qkvw + 2*DIMN + h*HD + jb*64;
    for (int t4 = tid; t4 < 2048; t4 += 256) {
        int dd = t4 >> 4, j4 = t4 & 15;
        *reinterpret_cast<float4*>(&ws[dd][j4*4]) =
            *reinterpret_cast<const float4*>(&wsrc[(chd*128 + dd)*QLD + j4*4]);
    }
    __syncthreads();
    float2 a0 = make_float2(0.f, 0.f), a1 = make_float2(0.f, 0.f);
    #pragma unroll 8
    for (int dd = 0; dd < 128; dd++) {
        float2 wv = *reinterpret_cast<const float2*>(&ws[dd][lane*2]);
        float t0 = ts[grp][dd], t1 = ts[grp + 8][dd];
        a0.x += t0*wv.x; a0.y += t0*wv.y;
        a1.x += t1*wv.x; a1.y += t1*wv.y;
    }
    int ocol = h*HD + jb*64 + lane*2;
    *reinterpret_cast<float2*>(&g_aop[chd][ grp     *DIMN + ocol]) = a0;
    *reinterpret_cast<float2*>(&g_aop[chd][(grp + 8)*DIMN + ocol]) = a1;
}

// Kernel 6b: reduce 16 chunk partials + bias -> g_ao. grid 128, block 256.
__global__ void k_ao_sum(const float* __restrict__ qkvb) {
    int idx = blockIdx.x * 256 + threadIdx.x;   // 0 .. 32767
    int col = idx & (DIMN-1);
    float a = qkvb[2*DIMN + col];
    #pragma unroll
    for (int c = 0; c < 16; c++) a += g_aop[c][idx];
    g_ao[idx] = a;
}

// ---------------------------------------------------------------------------
// Kernel 7a: partial proj over one d-chunk, 64 output cols per CTA.
// grid (32 eb, 16 chd), block 256. smem 40 KB.
__global__ void k_projp(const float* __restrict__ pw) {
    int eb = blockIdx.x, chd = blockIdx.y;
    int tid = threadIdx.x;
    int lane = tid & 31, grp = tid >> 5;
    __shared__ float as[16][128];
    __shared__ float ws[128][64];
    for (int t = tid; t < 2048; t += 256) {
        int bb = t >> 7, dd = t & 127;
        as[bb][dd] = g_ao[bb*DIMN + chd*128 + dd];
    }
    const float* wsrc = pw + eb*64;
    for (int t4 = tid; t4 < 2048; t4 += 256) {
        int dd = t4 >> 4, j4 = t4 & 15;
        *reinterpret_cast<float4*>(&ws[dd][j4*4]) =
            *reinterpret_cast<const float4*>(&wsrc[(chd*128 + dd)*DIMN + j4*4]);
    }
    __syncthreads();
    float2 a0 = make_float2(0.f, 0.f), a1 = make_float2(0.f, 0.f);
    #pragma unroll 8
    for (int dd = 0; dd < 128; dd++) {
        float2 wv = *reinterpret_cast<const float2*>(&ws[dd][lane*2]);
        float t0 = as[grp][dd], t1 = as[grp + 8][dd];
        a0.x += t0*wv.x; a0.y += t0*wv.y;
        a1.x += t1*wv.x; a1.y += t1*wv.y;
    }
    int e = eb*64 + lane*2;
    *reinterpret_cast<float2*>(&g_outp[chd][ grp     *DIMN + e]) = a0;
    *reinterpret_cast<float2*>(&g_outp[chd][(grp + 8)*DIMN + e]) = a1;
}

// Kernel 7b: reduce 16 chunk partials + bias -> out. grid 128, block 256.
__global__ void k_out_sum(const float* __restrict__ pb, float* __restrict__ out) {
    int idx = blockIdx.x * 256 + threadIdx.x;
    int e = idx & (DIMN-1);
    float a = pb[e];
    #pragma unroll
    for (int c = 0; c < 16; c++) a += g_outp[c][idx];
    out[idx] = a;
}

// ---------------------------------------------------------------------------
extern "C" void kernel_launch(void* const* d_in, const int* in_sizes, int n_in,
                              void* d_out, int out_size) {
    const float* x    = (const float*)d_in[0];
    const float* pos  = (const float*)d_in[1];
    const float* cls  = (const float*)d_in[2];
    const float* qkvw = (const float*)d_in[3];
    const float* qkvb = (const float*)d_in[4];
    const float* pw   = (const float*)d_in[5];
    const float* pb   = (const float*)d_in[6];
    float* out = (float*)d_out;

    k_q_part <<<dim3(16, 32), 128>>>(pos, cls, qkvw);
    k_q_sum  <<<16, 128>>>(qkvb);
    k_qhat   <<<dim3(256, 16), 256>>>(qkvw);
    k_spos   <<<dim3(32, 8), 256>>>(pos, cls);
    k_scores <<<dim3(32, 16), 256>>>(x);
    k_softmax<<<256, 128>>>(qkvb);
    k_t      <<<dim3(4, 16, 4), 256>>>(x, pos, cls);
    k_avp    <<<dim3(2, 16, 16), 256>>>(qkvw);
    k_ao_sum <<<128, 256>>>(qkvb);
    k_projp  <<<dim3(32, 16), 256>>>(pw);
    k_out_sum<<<128, 256>>>(pb, out);
}

// round 16
// speedup vs baseline: 1.1410x; 1.0827x over previous
#include <cuda_runtime.h>
#include <cstdint>

// Problem constants
#define BB    16
#define CC    8
#define DD    511
#define DIMN  2048
#define SEQ   512
#define NH    16
#define HD    128
#define HWSZ  256
#define XB    (CC*DD*HWSZ)   // 1046528  (x batch stride)
#define XC    (DD*HWSZ)      // 130816   (x channel stride)
#define QLD   6144           // qkv_w leading dim (row length)
#define SCALE 0.08838834764831845f  // 128^-0.5

// Scratch (static device globals; no allocation anywhere)
__device__ float g_qp[32*DIMN];        // split-K partials for q
__device__ float g_q[DIMN];            // q for cls token (batch-independent)
__device__ float g_qhat[NH*DIMN];      // scale * Wk_h^T q_h
__device__ float g_sposp[16][NH*SEQ];  // d-split partials of qhat.(pos+cls0)
__device__ float g_sc[BB*NH*SEQ];      // scores (x part) -> probs (in place)
__device__ float g_tp[4][BB*NH*DIMN];  // s-split partials of t = P @ tok
__device__ float g_aop[16][BB*DIMN];   // d-chunk partials of attn out @ Wv
__device__ float g_ao[BB*DIMN];        // attention output (pre-proj)
__device__ float g_outp[16][BB*DIMN];  // d-chunk partials of final proj

// ---- packed f32x2 helpers (Blackwell FFMA2 path; PTX-only per SASS docs) ----
__device__ __forceinline__ void fma2(unsigned long long& d,
                                     unsigned long long a, unsigned long long b) {
    asm("fma.rn.f32x2 %0, %1, %2, %0;" : "+l"(d) : "l"(a), "l"(b));
}
__device__ __forceinline__ unsigned long long add2(unsigned long long a,
                                                   unsigned long long b) {
    unsigned long long r;
    asm("add.rn.f32x2 %0, %1, %2;" : "=l"(r) : "l"(a), "l"(b));
    return r;
}
__device__ __forceinline__ unsigned long long bcast2(unsigned int b) {
    unsigned long long r;
    asm("mov.b64 %0, {%1, %1};" : "=l"(r) : "r"(b));
    return r;
}
__device__ __forceinline__ float f2lo(unsigned long long v) {
    return __uint_as_float((unsigned int)(v & 0xffffffffull));
}
__device__ __forceinline__ float f2hi(unsigned long long v) {
    return __uint_as_float((unsigned int)(v >> 32));
}

// ---------------------------------------------------------------------------
// Kernel 1a: split-K partial of q = tok0 @ Wq.
// grid (16 colblocks, 32 dchunks of 64 rows), block 128.
__global__ void k_q_part(const float* __restrict__ pos, const float* __restrict__ cls,
                         const float* __restrict__ qkvw) {
    __shared__ float t0[64];
    int dc = blockIdx.y;
    int tid = threadIdx.x;
    if (tid < 64) t0[tid] = cls[dc*64 + tid] + pos[dc*64 + tid];
    __syncthreads();
    int col = blockIdx.x * 128 + tid;
    const float* wp = qkvw + (dc*64)*QLD + col;
    float a0 = 0.f, a1 = 0.f, a2 = 0.f, a3 = 0.f;
    #pragma unroll 2
    for (int d = 0; d < 64; d += 8) {
        a0 += t0[d+0] * wp[(d+0)*QLD];
        a1 += t0[d+1] * wp[(d+1)*QLD];
        a2 += t0[d+2] * wp[(d+2)*QLD];
        a3 += t0[d+3] * wp[(d+3)*QLD];
        a0 += t0[d+4] * wp[(d+4)*QLD];
        a1 += t0[d+5] * wp[(d+5)*QLD];
        a2 += t0[d+6] * wp[(d+6)*QLD];
        a3 += t0[d+7] * wp[(d+7)*QLD];
    }
    g_qp[dc*DIMN + col] = (a0 + a1) + (a2 + a3);
}

// Kernel 1b: reduce the 32 partials (deterministic order) + bias. grid 16, block 128
__global__ void k_q_sum(const float* __restrict__ qkvb) {
    int col = blockIdx.x * 128 + threadIdx.x;
    float a = qkvb[col];
    #pragma unroll
    for (int dc = 0; dc < 32; dc++) a += g_qp[dc*DIMN + col];
    g_q[col] = a;
}

// ---------------------------------------------------------------------------
// Kernel 2: qhat[h, dim] = SCALE * sum_j qkv_w[dim, 2048 + h*128 + j] * q[h*128+j]
// grid (256, 16): 8 dims per CTA (one per warp), block 256, float4 loads.
__global__ void k_qhat(const float* __restrict__ qkvw) {
    int h = blockIdx.y;
    __shared__ float4 qv4[32];
    int tid = threadIdx.x;
    if (tid < 32) qv4[tid] = *reinterpret_cast<const float4*>(&g_q[h*HD + tid*4]);
    __syncthreads();
    int w = tid >> 5, lane = tid & 31;
    int dim = blockIdx.x * 8 + w;
    const float4* wr4 = reinterpret_cast<const float4*>(qkvw + dim*QLD + DIMN + h*HD);
    float4 wv = wr4[lane];
    float4 qv = qv4[lane];
    float p = wv.x*qv.x + wv.y*qv.y + wv.z*qv.z + wv.w*qv.w;
    #pragma unroll
    for (int o = 16; o; o >>= 1) p += __shfl_xor_sync(0xffffffffu, p, o);
    if (lane == 0) g_qhat[h*DIMN + dim] = p * SCALE;
}

// ---------------------------------------------------------------------------
// Kernel 2b: spos partials: g_sposp[ds][h,s] = qhat[h, ds*128:+128] . (pos[s] + [s==0]cls)
// grid (32 stiles, 16 dsplits of 128), block 256 (8 warps). Warp = 4 tokens x 8 heads.
__global__ void k_spos(const float* __restrict__ pos, const float* __restrict__ cls) {
    int ds = blockIdx.y;
    int b0 = ds * 128;          // dim base
    int tid = threadIdx.x, w = tid >> 5, lane = tid & 31;
    int tg = w >> 1;
    int hh = (w & 1) * 8;
    int s0 = blockIdx.x * 16 + tg * 4;
    __shared__ float qh[NH][128];   // 8 KB

    for (int t4 = tid; t4 < NH*32; t4 += 256) {
        int h = t4 >> 5, dd4 = t4 & 31;
        *reinterpret_cast<float4*>(&qh[h][dd4*4]) =
            *reinterpret_cast<const float4*>(&g_qhat[h*DIMN + b0 + dd4*4]);
    }
    __syncthreads();

    int dd = lane*4;
    int d  = b0 + dd;
    float4 tv[4];
    #pragma unroll
    for (int j = 0; j < 4; j++) {
        int s = s0 + j;
        float4 pv = *reinterpret_cast<const float4*>(&pos[s*DIMN + d]);
        if (s == 0) {
            float4 cv = *reinterpret_cast<const float4*>(&cls[d]);
            pv.x += cv.x; pv.y += cv.y; pv.z += cv.z; pv.w += cv.w;
        }
        tv[j] = pv;
    }
    float acc[8][4];
    #pragma unroll
    for (int h = 0; h < 8; h++) {
        float4 qv = *reinterpret_cast<const float4*>(&qh[hh + h][dd]);
        #pragma unroll
        for (int j = 0; j < 4; j++)
            acc[h][j] = qv.x*tv[j].x + qv.y*tv[j].y + qv.z*tv[j].z + qv.w*tv[j].w;
    }
    #pragma unroll
    for (int o = 16; o; o >>= 1)
        #pragma unroll
        for (int h = 0; h < 8; h++)
            #pragma unroll
            for (int j = 0; j < 4; j++)
                acc[h][j] += __shfl_xor_sync(0xffffffffu, acc[h][j], o);
    float outv = 0.f;
    #pragma unroll
    for (int h = 0; h < 8; h++)
        #pragma unroll
        for (int j = 0; j < 4; j++)
            if (lane == h*4 + j) outv = acc[h][j];
    int h8 = lane >> 2, j = lane & 3;
    g_sposp[ds][(hh + h8)*SEQ + s0 + j] = outv;
}

// ---------------------------------------------------------------------------
// Kernel 3: scores_x[b,h,s] = qhat[h,:] . x-part of tok[b,s,:]  (s=0 -> 0)
// grid (32 stiles, 16 b), block 256 (8 warps). Warp = 4 tokens x 8 heads.
// Packed f32x2 accumulators over dim pairs; double-buffered x prefetch. NO pos.
__global__ void __launch_bounds__(256, 2)
k_scores(const float* __restrict__ x) {
    int b = blockIdx.y;
    int tid = threadIdx.x, w = tid >> 5, lane = tid & 31;
    int tg = w >> 1;            // token group 0..3
    int hh = (w & 1) * 8;       // head base: 0 or 8
    int s0 = blockIdx.x * 16 + tg * 4;
    __shared__ float qh[NH * 512];   // 32 KB, current 512-dim chunk, all heads

    const ulonglong2 z2 = {0ull, 0ull};

    unsigned long long acc[8][4];   // packed (even-dim, odd-dim) partial sums
    #pragma unroll
    for (int h = 0; h < 8; h++)
        #pragma unroll
        for (int j = 0; j < 4; j++) acc[h][j] = 0ull;

    ulonglong2 xva[4], xvb[4];
    // prefetch x for slice 0
    {
        int d = lane*4;
        int c = d >> 8, r = d & 255;
        #pragma unroll
        for (int j = 0; j < 4; j++) {
            int s = s0 + j;
            xva[j] = (s == 0) ? z2
                   : *reinterpret_cast<const ulonglong2*>(&x[(size_t)b*XB + c*XC + (s-1)*HWSZ + r]);
        }
    }

    for (int ch = 0; ch < 4; ch++) {
        __syncthreads();
        // stage qhat chunk (float4)
        for (int t4 = tid; t4 < NH*128; t4 += 256) {
            int h = t4 >> 7, dd4 = t4 & 127;
            *reinterpret_cast<float4*>(&qh[h*512 + dd4*4]) =
                *reinterpret_cast<const float4*>(&g_qhat[h*DIMN + ch*512 + dd4*4]);
        }
        __syncthreads();
        #pragma unroll
        for (int it = 0; it < 4; it++) {
            int ci = ch*4 + it;                     // global slice 0..15
            ulonglong2* cur = (it & 1) ? xvb : xva; // parity static in it
            ulonglong2* nxt = (it & 1) ? xva : xvb;
            // prefetch next slice's x
            if (ci < 15) {
                int dn = (ci+1)*128 + lane*4;
                int cn = dn >> 8, rn = dn & 255;
                #pragma unroll
                for (int j = 0; j < 4; j++) {
                    int s = s0 + j;
                    nxt[j] = (s == 0) ? z2
                           : *reinterpret_cast<const ulonglong2*>(&x[(size_t)b*XB + cn*XC + (s-1)*HWSZ + rn]);
                }
            }
            // compute current slice: packed dot over dim pairs
            int dd = it*128 + lane*4;
            #pragma unroll
            for (int h = 0; h < 8; h++) {
                ulonglong2 qv = *reinterpret_cast<const ulonglong2*>(&qh[(hh + h)*512 + dd]);
                #pragma unroll
                for (int j = 0; j < 4; j++) {
                    fma2(acc[h][j], qv.x, cur[j].x);
                    fma2(acc[h][j], qv.y, cur[j].y);
                }
            }
        }
    }
    // unpack (lo+hi) then butterfly reduce (32 outputs per warp)
    float accf[8][4];
    #pragma unroll
    for (int h = 0; h < 8; h++)
        #pragma unroll
        for (int j = 0; j < 4; j++)
            accf[h][j] = f2lo(acc[h][j]) + f2hi(acc[h][j]);
    #pragma unroll
    for (int o = 16; o; o >>= 1)
        #pragma unroll
        for (int h = 0; h < 8; h++)
            #pragma unroll
            for (int j = 0; j < 4; j++)
                accf[h][j] += __shfl_xor_sync(0xffffffffu, accf[h][j], o);
    float outv = 0.f;
    #pragma unroll
    for (int h = 0; h < 8; h++)
        #pragma unroll
        for (int j = 0; j < 4; j++)
            if (lane == h*4 + j) outv = accf[h][j];
    int h8 = lane >> 2, j = lane & 3;
    g_sc[(b*NH + hh + h8)*SEQ + s0 + j] = outv;
}

// ---------------------------------------------------------------------------
// Kernel 4: softmax over s (512) per (b,h) row; adds q.bk bias + spos terms.
// grid 256, block 128
__global__ void k_softmax(const float* __restrict__ qkvb) {
    int bh = blockIdx.x;
    int h = bh & 15;
    int tid = threadIdx.x;
    __shared__ float red[128];

    red[tid] = g_q[h*HD + tid] * qkvb[DIMN + h*HD + tid];
    __syncthreads();
    for (int o = 64; o; o >>= 1) { if (tid < o) red[tid] += red[tid + o]; __syncthreads(); }
    float sbias = red[0] * SCALE;
    __syncthreads();

    float* row = g_sc + bh*SEQ;
    float v[4];
    // spos = sum of the 16 d-split partials (deterministic order)
    #pragma unroll
    for (int j = 0; j < 4; j++) {
        float sp = sbias;
        #pragma unroll
        for (int k = 0; k < 16; k++) sp += g_sposp[k][h*SEQ + tid + j*128];
        v[j] = row[tid + j*128] + sp;
    }
    float m = -1e30f;
    #pragma unroll
    for (int j = 0; j < 4; j++) m = fmaxf(m, v[j]);
    red[tid] = m; __syncthreads();
    for (int o = 64; o; o >>= 1) { if (tid < o) red[tid] = fmaxf(red[tid], red[tid + o]); __syncthreads(); }
    m = red[0];
    __syncthreads();
    float s = 0.f;
    #pragma unroll
    for (int j = 0; j < 4; j++) { v[j] = expf(v[j] - m); s += v[j]; }
    red[tid] = s; __syncthreads();
    for (int o = 64; o; o >>= 1) { if (tid < o) red[tid] += red[tid + o]; __syncthreads(); }
    float inv = 1.f / red[0];
    #pragma unroll
    for (int j = 0; j < 4; j++) row[tid + j*128] = v[j] * inv;
}

// ---------------------------------------------------------------------------
// Kernel 5: t partials: g_tp[sq][b,h,dim] over s in [sq*128, sq*128+128).
// grid (4 dchunks, 16 b, 4 sq), block 256. Warp = 128 dims x 8 heads; lane = 4 dims.
// Packed f32x2 over dim pairs; probs broadcast-packed in smem; x prefetch.
__global__ void __launch_bounds__(256, 2)
k_t(const float* __restrict__ x, const float* __restrict__ pos,
    const float* __restrict__ cls) {
    int b = blockIdx.y, sq = blockIdx.z;
    int tid = threadIdx.x, w = tid >> 5, lane = tid & 31;
    int dg = w >> 1;            // dim group 0..3
    int hh = (w & 1) * 8;       // head base
    int dim = blockIdx.x*512 + dg*128 + lane*4;
    int sbase = sq * 128;
    __shared__ unsigned long long ps2[NH][128];   // 16 KB broadcast-packed probs
    for (int t = tid; t < NH*128; t += 256) {
        int h = t >> 7, ss = t & 127;
        ps2[h][ss] = bcast2(__float_as_uint(g_sc[(b*NH + h)*SEQ + sbase + ss]));
    }
    __syncthreads();

    int c = dim >> 8, r = dim & 255;          // 4 dims share channel c
    const float* xp = x + (size_t)b*XB + c*XC + r;   // token s>=1 -> xp + (s-1)*HWSZ
    const float* pp = pos + dim;

    unsigned long long acc2[8][2];   // [h][dim-pair]: (d0,d1) and (d2,d3)
    #pragma unroll
    for (int h = 0; h < 8; h++) { acc2[h][0] = 0ull; acc2[h][1] = 0ull; }

    ulonglong2 xa[4], xb[4];
    // preload k=0 tokens (s = sbase..sbase+3; s==0 only when sq==0)
    #pragma unroll
    for (int j = 0; j < 4; j++) {
        int s = sbase + j;
        xa[j] = (s == 0) ? *reinterpret_cast<const ulonglong2*>(&cls[dim])
                         : *reinterpret_cast<const ulonglong2*>(&xp[(s-1)*HWSZ]);
    }

    #pragma unroll 4
    for (int k2 = 0; k2 < 16; k2++) {
        int k = k2*2;
        // prefetch k+1 (s >= 1 always)
        {
            int s = sbase + (k+1)*4;
            #pragma unroll
            for (int j = 0; j < 4; j++)
                xb[j] = *reinterpret_cast<const ulonglong2*>(&xp[(s + j - 1)*HWSZ]);
        }
        // compute k from xa
        {
            int s = sbase + k*4;
            ulonglong2 tv[4];
            #pragma unroll
            for (int j = 0; j < 4; j++) {
                ulonglong2 pv = *reinterpret_cast<const ulonglong2*>(&pp[(size_t)(s + j)*DIMN]);
                tv[j].x = add2(xa[j].x, pv.x);
                tv[j].y = add2(xa[j].y, pv.y);
            }
            #pragma unroll
            for (int h = 0; h < 8; h++) {
                ulonglong2 p01 = *reinterpret_cast<const ulonglong2*>(&ps2[hh + h][k*4]);
                ulonglong2 p23 = *reinterpret_cast<const ulonglong2*>(&ps2[hh + h][k*4 + 2]);
                fma2(acc2[h][0], p01.x, tv[0].x); fma2(acc2[h][1], p01.x, tv[0].y);
                fma2(acc2[h][0], p01.y, tv[1].x); fma2(acc2[h][1], p01.y, tv[1].y);
                fma2(acc2[h][0], p23.x, tv[2].x); fma2(acc2[h][1], p23.x, tv[2].y);
                fma2(acc2[h][0], p23.y, tv[3].x); fma2(acc2[h][1], p23.y, tv[3].y);
            }
        }
        // prefetch k+2 into xa
        if (k2 < 15) {
            int s = sbase + (k+2)*4;
            #pragma unroll
            for (int j = 0; j < 4; j++)
                xa[j] = *reinterpret_cast<const ulonglong2*>(&xp[(s + j - 1)*HWSZ]);
        }
        // compute k+1 from xb
        {
            int s = sbase + (k+1)*4;
            ulonglong2 tv[4];
            #pragma unroll
            for (int j = 0; j < 4; j++) {
                ulonglong2 pv = *reinterpret_cast<const ulonglong2*>(&pp[(size_t)(s + j)*DIMN]);
                tv[j].x = add2(xb[j].x, pv.x);
                tv[j].y = add2(xb[j].y, pv.y);
            }
            #pragma unroll
            for (int h = 0; h < 8; h++) {
                ulonglong2 p01 = *reinterpret_cast<const ulonglong2*>(&ps2[hh + h][(k+1)*4]);
                ulonglong2 p23 = *reinterpret_cast<const ulonglong2*>(&ps2[hh + h][(k+1)*4 + 2]);
                fma2(acc2[h][0], p01.x, tv[0].x); fma2(acc2[h][1], p01.x, tv[0].y);
                fma2(acc2[h][0], p01.y, tv[1].x); fma2(acc2[h][1], p01.y, tv[1].y);
                fma2(acc2[h][0], p23.x, tv[2].x); fma2(acc2[h][1], p23.x, tv[2].y);
                fma2(acc2[h][0], p23.y, tv[3].x); fma2(acc2[h][1], p23.y, tv[3].y);
            }
        }
    }
    #pragma unroll
    for (int h = 0; h < 8; h++) {
        float4 o = make_float4(f2lo(acc2[h][0]), f2hi(acc2[h][0]),
                               f2lo(acc2[h][1]), f2hi(acc2[h][1]));
        *reinterpret_cast<float4*>(&g_tp[sq][(b*NH + hh + h)*DIMN + dim]) = o;
    }
}

// ---------------------------------------------------------------------------
// Kernel 6a: partial ao over one d-chunk, 64 output cols per CTA.
// Sums the 4 s-partials of t while staging.
// grid (2 jb, 16 h, 16 chd), block 256. smem 40 KB.
__global__ void k_avp(const float* __restrict__ qkvw) {
    int jb = blockIdx.x, h = blockIdx.y, chd = blockIdx.z;
    int tid = threadIdx.x;
    int lane = tid & 31, grp = tid >> 5;  // grp: b = grp and grp+8
    __shared__ float ts[16][128];
    __shared__ float ws[128][64];
    // stage t tile, summing s-partials (deterministic order)
    for (int t = tid; t < 2048; t += 256) {
        int bb = t >> 7, dd = t & 127;
        int idx = (bb*NH + h)*DIMN + chd*128 + dd;
        ts[bb][dd] = (g_tp[0][idx] + g_tp[1][idx]) + (g_tp[2][idx] + g_tp[3][idx]);
    }
    // stage Wv tile (128 rows x 64 cols), float4
    const float* wsrc = qkvw + 2*DIMN + h*HD + jb*64;
    for (int t4 = tid; t4 < 2048; t4 += 256) {
        int dd = t4 >> 4, j4 = t4 & 15;
        *reinterpret_cast<float4*>(&ws[dd][j4*4]) =
            *reinterpret_cast<const float4*>(&wsrc[(chd*128 + dd)*QLD + j4*4]);
    }
    __syncthreads();
    float2 a0 = make_float2(0.f, 0.f), a1 = make_float2(0.f, 0.f);
    #pragma unroll 8
    for (int dd = 0; dd < 128; dd++) {
        float2 wv = *reinterpret_cast<const float2*>(&ws[dd][lane*2]);
        float t0 = ts[grp][dd], t1 = ts[grp + 8][dd];
        a0.x += t0*wv.x; a0.y += t0*wv.y;
        a1.x += t1*wv.x; a1.y += t1*wv.y;
    }
    int ocol = h*HD + jb*64 + lane*2;
    *reinterpret_cast<float2*>(&g_aop[chd][ grp     *DIMN + ocol]) = a0;
    *reinterpret_cast<float2*>(&g_aop[chd][(grp + 8)*DIMN + ocol]) = a1;
}

// Kernel 6b: reduce 16 chunk partials + bias -> g_ao. grid 128, block 256.
__global__ void k_ao_sum(const float* __restrict__ qkvb) {
    int idx = blockIdx.x * 256 + threadIdx.x;   // 0 .. 32767
    int col = idx & (DIMN-1);
    float a = qkvb[2*DIMN + col];
    #pragma unroll
    for (int c = 0; c < 16; c++) a += g_aop[c][idx];
    g_ao[idx] = a;
}

// ---------------------------------------------------------------------------
// Kernel 7a: partial proj over one d-chunk, 64 output cols per CTA.
// grid (32 eb, 16 chd), block 256. smem 40 KB.
__global__ void k_projp(const float* __restrict__ pw) {
    int eb = blockIdx.x, chd = blockIdx.y;
    int tid = threadIdx.x;
    int lane = tid & 31, grp = tid >> 5;
    __shared__ float as[16][128];
    __shared__ float ws[128][64];
    for (int t = tid; t < 2048; t += 256) {
        int bb = t >> 7, dd = t & 127;
        as[bb][dd] = g_ao[bb*DIMN + chd*128 + dd];
    }
    const float* wsrc = pw + eb*64;
    for (int t4 = tid; t4 < 2048; t4 += 256) {
        int dd = t4 >> 4, j4 = t4 & 15;
        *reinterpret_cast<float4*>(&ws[dd][j4*4]) =
            *reinterpret_cast<const float4*>(&wsrc[(chd*128 + dd)*DIMN + j4*4]);
    }
    __syncthreads();
    float2 a0 = make_float2(0.f, 0.f), a1 = make_float2(0.f, 0.f);
    #pragma unroll 8
    for (int dd = 0; dd < 128; dd++) {
        float2 wv = *reinterpret_cast<const float2*>(&ws[dd][lane*2]);
        float t0 = as[grp][dd], t1 = as[grp + 8][dd];
        a0.x += t0*wv.x; a0.y += t0*wv.y;
        a1.x += t1*wv.x; a1.y += t1*wv.y;
    }
    int e = eb*64 + lane*2;
    *reinterpret_cast<float2*>(&g_outp[chd][ grp     *DIMN + e]) = a0;
    *reinterpret_cast<float2*>(&g_outp[chd][(grp + 8)*DIMN + e]) = a1;
}

// Kernel 7b: reduce 16 chunk partials + bias -> out. grid 128, block 256.
__global__ void k_out_sum(const float* __restrict__ pb, float* __restrict__ out) {
    int idx = blockIdx.x * 256 + threadIdx.x;
    int e = idx & (DIMN-1);
    float a = pb[e];
    #pragma unroll
    for (int c = 0; c < 16; c++) a += g_outp[c][idx];
    out[idx] = a;
}

// ---------------------------------------------------------------------------
extern "C" void kernel_launch(void* const* d_in, const int* in_sizes, int n_in,
                              void* d_out, int out_size) {
    const float* x    = (const float*)d_in[0];
    const float* pos  = (const float*)d_in[1];
    const float* cls  = (const float*)d_in[2];
    const float* qkvw = (const float*)d_in[3];
    const float* qkvb = (const float*)d_in[4];
    const float* pw   = (const float*)d_in[5];
    const float* pb   = (const float*)d_in[6];
    float* out = (float*)d_out;

    k_q_part <<<dim3(16, 32), 128>>>(pos, cls, qkvw);
    k_q_sum  <<<16, 128>>>(qkvb);
    k_qhat   <<<dim3(256, 16), 256>>>(qkvw);
    k_spos   <<<dim3(32, 16), 256>>>(pos, cls);
    k_scores <<<dim3(32, 16), 256>>>(x);
    k_softmax<<<256, 128>>>(qkvb);
    k_t      <<<dim3(4, 16, 4), 256>>>(x, pos, cls);
    k_avp    <<<dim3(2, 16, 16), 256>>>(qkvw);
    k_ao_sum <<<128, 256>>>(qkvb);
    k_projp  <<<dim3(32, 16), 256>>>(pw);
    k_out_sum<<<128, 256>>>(pb, out);
}

// round 17
// speedup vs baseline: 1.1569x; 1.0139x over previous
#include <cuda_runtime.h>
#include <cstdint>

// Problem constants
#define BB    16
#define CC    8
#define DD    511
#define DIMN  2048
#define SEQ   512
#define NH    16
#define HD    128
#define HWSZ  256
#define XB    (CC*DD*HWSZ)   // 1046528  (x batch stride)
#define XC    (DD*HWSZ)      // 130816   (x channel stride)
#define QLD   6144           // qkv_w leading dim (row length)
#define SCALE 0.08838834764831845f  // 128^-0.5

// Scratch (static device globals; no allocation anywhere)
__device__ float g_qp[32*DIMN];          // split-K partials for q
__device__ float g_q[DIMN];              // q for cls token (batch-independent)
__device__ float g_qhat[NH*DIMN];        // scale * Wk_h^T q_h
__device__ float g_sc[(BB+1)*NH*SEQ];    // scores (x part) -> probs; row 16 = spos
__device__ float g_tp[4][BB*NH*DIMN];    // s-split partials of t = P @ tok
__device__ float g_aop[16][BB*DIMN];     // d-chunk partials of attn out @ Wv
__device__ float g_ao[BB*DIMN];          // attention output (pre-proj)
__device__ float g_outp[16][BB*DIMN];    // d-chunk partials of final proj

// ---- packed f32x2 helpers (Blackwell FFMA2 path; PTX-only per SASS docs) ----
__device__ __forceinline__ void fma2(unsigned long long& d,
                                     unsigned long long a, unsigned long long b) {
    asm("fma.rn.f32x2 %0, %1, %2, %0;" : "+l"(d) : "l"(a), "l"(b));
}
__device__ __forceinline__ unsigned long long add2(unsigned long long a,
                                                   unsigned long long b) {
    unsigned long long r;
    asm("add.rn.f32x2 %0, %1, %2;" : "=l"(r) : "l"(a), "l"(b));
    return r;
}
__device__ __forceinline__ unsigned long long bcast2(unsigned int b) {
    unsigned long long r;
    asm("mov.b64 %0, {%1, %1};" : "=l"(r) : "r"(b));
    return r;
}
__device__ __forceinline__ float f2lo(unsigned long long v) {
    return __uint_as_float((unsigned int)(v & 0xffffffffull));
}
__device__ __forceinline__ float f2hi(unsigned long long v) {
    return __uint_as_float((unsigned int)(v >> 32));
}

// ---------------------------------------------------------------------------
// Kernel 1a: split-K partial of q = tok0 @ Wq.
// grid (16 colblocks, 32 dchunks of 64 rows), block 128.
__global__ void k_q_part(const float* __restrict__ pos, const float* __restrict__ cls,
                         const float* __restrict__ qkvw) {
    __shared__ float t0[64];
    int dc = blockIdx.y;
    int tid = threadIdx.x;
    if (tid < 64) t0[tid] = cls[dc*64 + tid] + pos[dc*64 + tid];
    __syncthreads();
    int col = blockIdx.x * 128 + tid;
    const float* wp = qkvw + (dc*64)*QLD + col;
    float a0 = 0.f, a1 = 0.f, a2 = 0.f, a3 = 0.f;
    #pragma unroll 2
    for (int d = 0; d < 64; d += 8) {
        a0 += t0[d+0] * wp[(d+0)*QLD];
        a1 += t0[d+1] * wp[(d+1)*QLD];
        a2 += t0[d+2] * wp[(d+2)*QLD];
        a3 += t0[d+3] * wp[(d+3)*QLD];
        a0 += t0[d+4] * wp[(d+4)*QLD];
        a1 += t0[d+5] * wp[(d+5)*QLD];
        a2 += t0[d+6] * wp[(d+6)*QLD];
        a3 += t0[d+7] * wp[(d+7)*QLD];
    }
    g_qp[dc*DIMN + col] = (a0 + a1) + (a2 + a3);
}

// Kernel 1b: reduce the 32 partials (deterministic order) + bias. grid 16, block 128
__global__ void k_q_sum(const float* __restrict__ qkvb) {
    int col = blockIdx.x * 128 + threadIdx.x;
    float a = qkvb[col];
    #pragma unroll
    for (int dc = 0; dc < 32; dc++) a += g_qp[dc*DIMN + col];
    g_q[col] = a;
}

// ---------------------------------------------------------------------------
// Kernel 2: qhat[h, dim] = SCALE * sum_j qkv_w[dim, 2048 + h*128 + j] * q[h*128+j]
// grid (256, 16): 8 dims per CTA (one per warp), block 256, float4 loads.
__global__ void k_qhat(const float* __restrict__ qkvw) {
    int h = blockIdx.y;
    __shared__ float4 qv4[32];
    int tid = threadIdx.x;
    if (tid < 32) qv4[tid] = *reinterpret_cast<const float4*>(&g_q[h*HD + tid*4]);
    __syncthreads();
    int w = tid >> 5, lane = tid & 31;
    int dim = blockIdx.x * 8 + w;
    const float4* wr4 = reinterpret_cast<const float4*>(qkvw + dim*QLD + DIMN + h*HD);
    float4 wv = wr4[lane];
    float4 qv = qv4[lane];
    float p = wv.x*qv.x + wv.y*qv.y + wv.z*qv.z + wv.w*qv.w;
    #pragma unroll
    for (int o = 16; o; o >>= 1) p += __shfl_xor_sync(0xffffffffu, p, o);
    if (lane == 0) g_qhat[h*DIMN + dim] = p * SCALE;
}

// ---------------------------------------------------------------------------
// Kernel 3: scores_x[b,h,s] = qhat[h,:] . x-part of tok[b,s,:]
//   b < 16 : x-part = x[b,s-1]           (s=0 -> 0)
//   b == 16: x-part = pos[s] (+cls at s=0)  -> spos row, batch-independent
// grid (32 stiles, 17 b), block 256 (8 warps). Warp = 4 tokens x 8 heads.
// Packed f32x2 accumulators over dim pairs; double-buffered prefetch.
__global__ void __launch_bounds__(256, 2)
k_scores(const float* __restrict__ x, const float* __restrict__ pos,
         const float* __restrict__ cls) {
    int b = blockIdx.y;
    int tid = threadIdx.x, w = tid >> 5, lane = tid & 31;
    int tg = w >> 1;            // token group 0..3
    int hh = (w & 1) * 8;       // head base: 0 or 8
    int s0 = blockIdx.x * 16 + tg * 4;
    bool isPos = (b == BB);
    __shared__ float qh[NH * 512];   // 32 KB, current 512-dim chunk, all heads

    const ulonglong2 z2 = {0ull, 0ull};

    // loader for one (slice-dim-base, token) -> 16B of the "x-part"
    auto ldx = [&](int d, int s) -> ulonglong2 {
        if (isPos) {
            ulonglong2 pv = *reinterpret_cast<const ulonglong2*>(&pos[(size_t)s*DIMN + d]);
            if (s == 0) {
                ulonglong2 cv = *reinterpret_cast<const ulonglong2*>(&cls[d]);
                pv.x = add2(pv.x, cv.x);
                pv.y = add2(pv.y, cv.y);
            }
            return pv;
        }
        if (s == 0) return z2;
        int c = d >> 8, r = d & 255;
        return *reinterpret_cast<const ulonglong2*>(&x[(size_t)b*XB + c*XC + (s-1)*HWSZ + r]);
    };

    unsigned long long acc[8][4];   // packed (even-dim, odd-dim) partial sums
    #pragma unroll
    for (int h = 0; h < 8; h++)
        #pragma unroll
        for (int j = 0; j < 4; j++) acc[h][j] = 0ull;

    ulonglong2 xva[4], xvb[4];
    // prefetch for slice 0
    #pragma unroll
    for (int j = 0; j < 4; j++) xva[j] = ldx(lane*4, s0 + j);

    for (int ch = 0; ch < 4; ch++) {
        __syncthreads();
        // stage qhat chunk (float4)
        for (int t4 = tid; t4 < NH*128; t4 += 256) {
            int h = t4 >> 7, dd4 = t4 & 127;
            *reinterpret_cast<float4*>(&qh[h*512 + dd4*4]) =
                *reinterpret_cast<const float4*>(&g_qhat[h*DIMN + ch*512 + dd4*4]);
        }
        __syncthreads();
        #pragma unroll
        for (int it = 0; it < 4; it++) {
            int ci = ch*4 + it;                     // global slice 0..15
            ulonglong2* cur = (it & 1) ? xvb : xva; // parity static in it
            ulonglong2* nxt = (it & 1) ? xva : xvb;
            // prefetch next slice
            if (ci < 15) {
                int dn = (ci+1)*128 + lane*4;
                #pragma unroll
                for (int j = 0; j < 4; j++) nxt[j] = ldx(dn, s0 + j);
            }
            // compute current slice: packed dot over dim pairs
            int dd = it*128 + lane*4;
            #pragma unroll
            for (int h = 0; h < 8; h++) {
                ulonglong2 qv = *reinterpret_cast<const ulonglong2*>(&qh[(hh + h)*512 + dd]);
                #pragma unroll
                for (int j = 0; j < 4; j++) {
                    fma2(acc[h][j], qv.x, cur[j].x);
                    fma2(acc[h][j], qv.y, cur[j].y);
                }
            }
        }
    }
    // unpack (lo+hi) then butterfly reduce (32 outputs per warp)
    float accf[8][4];
    #pragma unroll
    for (int h = 0; h < 8; h++)
        #pragma unroll
        for (int j = 0; j < 4; j++)
            accf[h][j] = f2lo(acc[h][j]) + f2hi(acc[h][j]);
    #pragma unroll
    for (int o = 16; o; o >>= 1)
        #pragma unroll
        for (int h = 0; h < 8; h++)
            #pragma unroll
            for (int j = 0; j < 4; j++)
                accf[h][j] += __shfl_xor_sync(0xffffffffu, accf[h][j], o);
    float outv = 0.f;
    #pragma unroll
    for (int h = 0; h < 8; h++)
        #pragma unroll
        for (int j = 0; j < 4; j++)
            if (lane == h*4 + j) outv = accf[h][j];
    int h8 = lane >> 2, j = lane & 3;
    g_sc[(b*NH + hh + h8)*SEQ + s0 + j] = outv;
}

// ---------------------------------------------------------------------------
// Kernel 4: softmax over s (512) per (b,h) row; adds q.bk bias + spos row.
// grid 256, block 128
__global__ void k_softmax(const float* __restrict__ qkvb) {
    int bh = blockIdx.x;
    int h = bh & 15;
    int tid = threadIdx.x;
    __shared__ float red[128];

    red[tid] = g_q[h*HD + tid] * qkvb[DIMN + h*HD + tid];
    __syncthreads();
    for (int o = 64; o; o >>= 1) { if (tid < o) red[tid] += red[tid + o]; __syncthreads(); }
    float sbias = red[0] * SCALE;
    __syncthreads();

    float* row = g_sc + bh*SEQ;
    const float* spos = g_sc + (BB*NH + h)*SEQ;   // batch-16 row = qhat.(pos+cls0)
    float v[4];
    #pragma unroll
    for (int j = 0; j < 4; j++)
        v[j] = row[tid + j*128] + spos[tid + j*128] + sbias;
    float m = -1e30f;
    #pragma unroll
    for (int j = 0; j < 4; j++) m = fmaxf(m, v[j]);
    red[tid] = m; __syncthreads();
    for (int o = 64; o; o >>= 1) { if (tid < o) red[tid] = fmaxf(red[tid], red[tid + o]); __syncthreads(); }
    m = red[0];
    __syncthreads();
    float s = 0.f;
    #pragma unroll
    for (int j = 0; j < 4; j++) { v[j] = expf(v[j] - m); s += v[j]; }
    red[tid] = s; __syncthreads();
    for (int o = 64; o; o >>= 1) { if (tid < o) red[tid] += red[tid + o]; __syncthreads(); }
    float inv = 1.f / red[0];
    #pragma unroll
    for (int j = 0; j < 4; j++) row[tid + j*128] = v[j] * inv;
}

// ---------------------------------------------------------------------------
// Kernel 5: t partials: g_tp[sq][b,h,dim] over s in [sq*128, sq*128+128).
// grid (4 dchunks, 16 b, 4 sq), block 256. Warp = 128 dims x 8 heads; lane = 4 dims.
// Packed f32x2 over dim pairs; probs broadcast-packed in smem; x prefetch.
__global__ void __launch_bounds__(256, 2)
k_t(const float* __restrict__ x, const float* __restrict__ pos,
    const float* __restrict__ cls) {
    int b = blockIdx.y, sq = blockIdx.z;
    int tid = threadIdx.x, w = tid >> 5, lane = tid & 31;
    int dg = w >> 1;            // dim group 0..3
    int hh = (w & 1) * 8;       // head base
    int dim = blockIdx.x*512 + dg*128 + lane*4;
    int sbase = sq * 128;
    __shared__ unsigned long long ps2[NH][128];   // 16 KB broadcast-packed probs
    for (int t = tid; t < NH*128; t += 256) {
        int h = t >> 7, ss = t & 127;
        ps2[h][ss] = bcast2(__float_as_uint(g_sc[(b*NH + h)*SEQ + sbase + ss]));
    }
    __syncthreads();

    int c = dim >> 8, r = dim & 255;          // 4 dims share channel c
    const float* xp = x + (size_t)b*XB + c*XC + r;   // token s>=1 -> xp + (s-1)*HWSZ
    const float* pp = pos + dim;

    unsigned long long acc2[8][2];   // [h][dim-pair]: (d0,d1) and (d2,d3)
    #pragma unroll
    for (int h = 0; h < 8; h++) { acc2[h][0] = 0ull; acc2[h][1] = 0ull; }

    ulonglong2 xa[4], xb[4];
    // preload k=0 tokens (s = sbase..sbase+3; s==0 only when sq==0)
    #pragma unroll
    for (int j = 0; j < 4; j++) {
        int s = sbase + j;
        xa[j] = (s == 0) ? *reinterpret_cast<const ulonglong2*>(&cls[dim])
                         : *reinterpret_cast<const ulonglong2*>(&xp[(s-1)*HWSZ]);
    }

    #pragma unroll 4
    for (int k2 = 0; k2 < 16; k2++) {
        int k = k2*2;
        // prefetch k+1 (s >= 1 always)
        {
            int s = sbase + (k+1)*4;
            #pragma unroll
            for (int j = 0; j < 4; j++)
                xb[j] = *reinterpret_cast<const ulonglong2*>(&xp[(s + j - 1)*HWSZ]);
        }
        // compute k from xa
        {
            int s = sbase + k*4;
            ulonglong2 tv[4];
            #pragma unroll
            for (int j = 0; j < 4; j++) {
                ulonglong2 pv = *reinterpret_cast<const ulonglong2*>(&pp[(size_t)(s + j)*DIMN]);
                tv[j].x = add2(xa[j].x, pv.x);
                tv[j].y = add2(xa[j].y, pv.y);
            }
            #pragma unroll
            for (int h = 0; h < 8; h++) {
                ulonglong2 p01 = *reinterpret_cast<const ulonglong2*>(&ps2[hh + h][k*4]);
                ulonglong2 p23 = *reinterpret_cast<const ulonglong2*>(&ps2[hh + h][k*4 + 2]);
                fma2(acc2[h][0], p01.x, tv[0].x); fma2(acc2[h][1], p01.x, tv[0].y);
                fma2(acc2[h][0], p01.y, tv[1].x); fma2(acc2[h][1], p01.y, tv[1].y);
                fma2(acc2[h][0], p23.x, tv[2].x); fma2(acc2[h][1], p23.x, tv[2].y);
                fma2(acc2[h][0], p23.y, tv[3].x); fma2(acc2[h][1], p23.y, tv[3].y);
            }
        }
        // prefetch k+2 into xa
        if (k2 < 15) {
            int s = sbase + (k+2)*4;
            #pragma unroll
            for (int j = 0; j < 4; j++)
                xa[j] = *reinterpret_cast<const ulonglong2*>(&xp[(s + j - 1)*HWSZ]);
        }
        // compute k+1 from xb
        {
            int s = sbase + (k+1)*4;
            ulonglong2 tv[4];
            #pragma unroll
            for (int j = 0; j < 4; j++) {
                ulonglong2 pv = *reinterpret_cast<const ulonglong2*>(&pp[(size_t)(s + j)*DIMN]);
                tv[j].x = add2(xb[j].x, pv.x);
                tv[j].y = add2(xb[j].y, pv.y);
            }
            #pragma unroll
            for (int h = 0; h < 8; h++) {
                ulonglong2 p01 = *reinterpret_cast<const ulonglong2*>(&ps2[hh + h][(k+1)*4]);
                ulonglong2 p23 = *reinterpret_cast<const ulonglong2*>(&ps2[hh + h][(k+1)*4 + 2]);
                fma2(acc2[h][0], p01.x, tv[0].x); fma2(acc2[h][1], p01.x, tv[0].y);
                fma2(acc2[h][0], p01.y, tv[1].x); fma2(acc2[h][1], p01.y, tv[1].y);
                fma2(acc2[h][0], p23.x, tv[2].x); fma2(acc2[h][1], p23.x, tv[2].y);
                fma2(acc2[h][0], p23.y, tv[3].x); fma2(acc2[h][1], p23.y, tv[3].y);
            }
        }
    }
    #pragma unroll
    for (int h = 0; h < 8; h++) {
        float4 o = make_float4(f2lo(acc2[h][0]), f2hi(acc2[h][0]),
                               f2lo(acc2[h][1]), f2hi(acc2[h][1]));
        *reinterpret_cast<float4*>(&g_tp[sq][(b*NH + hh + h)*DIMN + dim]) = o;
    }
}

// ---------------------------------------------------------------------------
// Kernel 6a: partial ao over one d-chunk, 64 output cols per CTA.
// Sums the 4 s-partials of t while staging.
// grid (2 jb, 16 h, 16 chd), block 256. smem 40 KB.
__global__ void k_avp(const float* __restrict__ qkvw) {
    int jb = blockIdx.x, h = blockIdx.y, chd = blockIdx.z;
    int tid = threadIdx.x;
    int lane = tid & 31, grp = tid >> 5;  // grp: b = grp and grp+8
    __shared__ float ts[16][128];
    __shared__ float ws[128][64];
    // stage t tile, summing s-partials (deterministic order)
    for (int t = tid; t < 2048; t += 256) {
        int bb = t >> 7, dd = t & 127;
        int idx = (bb*NH + h)*DIMN + chd*128 + dd;
        ts[bb][dd] = (g_tp[0][idx] + g_tp[1][idx]) + (g_tp[2][idx] + g_tp[3][idx]);
    }
    // stage Wv tile (128 rows x 64 cols), float4
    const float* wsrc = qkvw + 2*DIMN + h*HD + jb*64;
    for (int t4 = tid; t4 < 2048; t4 += 256) {
        int dd = t4 >> 4, j4 = t4 & 15;
        *reinterpret_cast<float4*>(&ws[dd][j4*4]) =
            *reinterpret_cast<const float4*>(&wsrc[(chd*128 + dd)*QLD + j4*4]);
    }
    __syncthreads();
    float2 a0 = make_float2(0.f, 0.f), a1 = make_float2(0.f, 0.f);
    #pragma unroll 8
    for (int dd = 0; dd < 128; dd++) {
        float2 wv = *reinterpret_cast<const float2*>(&ws[dd][lane*2]);
        float t0 = ts[grp][dd], t1 = ts[grp + 8][dd];
        a0.x += t0*wv.x; a0.y += t0*wv.y;
        a1.x += t1*wv.x; a1.y += t1*wv.y;
    }
    int ocol = h*HD + jb*64 + lane*2;
    *reinterpret_cast<float2*>(&g_aop[chd][ grp     *DIMN + ocol]) = a0;
    *reinterpret_cast<float2*>(&g_aop[chd][(grp + 8)*DIMN + ocol]) = a1;
}

// Kernel 6b: reduce 16 chunk partials + bias -> g_ao. grid 128, block 256.
__global__ void k_ao_sum(const float* __restrict__ qkvb) {
    int idx = blockIdx.x * 256 + threadIdx.x;   // 0 .. 32767
    int col = idx & (DIMN-1);
    float a = qkvb[2*DIMN + col];
    #pragma unroll
    for (int c = 0; c < 16; c++) a += g_aop[c][idx];
    g_ao[idx] = a;
}

// ---------------------------------------------------------------------------
// Kernel 7a: partial proj over one d-chunk, 64 output cols per CTA.
// grid (32 eb, 16 chd), block 256. smem 40 KB.
__global__ void k_projp(const float* __restrict__ pw) {
    int eb = blockIdx.x, chd = blockIdx.y;
    int tid = threadIdx.x;
    int lane = tid & 31, grp = tid >> 5;
    __shared__ float as[16][128];
    __shared__ float ws[128][64];
    for (int t = tid; t < 2048; t += 256) {
        int bb = t >> 7, dd = t & 127;
        as[bb][dd] = g_ao[bb*DIMN + chd*128 + dd];
    }
    const float* wsrc = pw + eb*64;
    for (int t4 = tid; t4 < 2048; t4 += 256) {
        int dd = t4 >> 4, j4 = t4 & 15;
        *reinterpret_cast<float4*>(&ws[dd][j4*4]) =
            *reinterpret_cast<const float4*>(&wsrc[(chd*128 + dd)*DIMN + j4*4]);
    }
    __syncthreads();
    float2 a0 = make_float2(0.f, 0.f), a1 = make_float2(0.f, 0.f);
    #pragma unroll 8
    for (int dd = 0; dd < 128; dd++) {
        float2 wv = *reinterpret_cast<const float2*>(&ws[dd][lane*2]);
        float t0 = as[grp][dd], t1 = as[grp + 8][dd];
        a0.x += t0*wv.x; a0.y += t0*wv.y;
        a1.x += t1*wv.x; a1.y += t1*wv.y;
    }
    int e = eb*64 + lane*2;
    *reinterpret_cast<float2*>(&g_outp[chd][ grp     *DIMN + e]) = a0;
    *reinterpret_cast<float2*>(&g_outp[chd][(grp + 8)*DIMN + e]) = a1;
}

// Kernel 7b: reduce 16 chunk partials + bias -> out. grid 128, block 256.
__global__ void k_out_sum(const float* __restrict__ pb, float* __restrict__ out) {
    int idx = blockIdx.x * 256 + threadIdx.x;
    int e = idx & (DIMN-1);
    float a = pb[e];
    #pragma unroll
    for (int c = 0; c < 16; c++) a += g_outp[c][idx];
    out[idx] = a;
}

// ---------------------------------------------------------------------------
extern "C" void kernel_launch(void* const* d_in, const int* in_sizes, int n_in,
                              void* d_out, int out_size) {
    const float* x    = (const float*)d_in[0];
    const float* pos  = (const float*)d_in[1];
    const float* cls  = (const float*)d_in[2];
    const float* qkvw = (const float*)d_in[3];
    const float* qkvb = (const float*)d_in[4];
    const float* pw   = (const float*)d_in[5];
    const float* pb   = (const float*)d_in[6];
    float* out = (float*)d_out;

    k_q_part <<<dim3(16, 32), 128>>>(pos, cls, qkvw);
    k_q_sum  <<<16, 128>>>(qkvb);
    k_qhat   <<<dim3(256, 16), 256>>>(qkvw);
    k_scores <<<dim3(32, 17), 256>>>(x, pos, cls);
    k_softmax<<<256, 128>>>(qkvb);
    k_t      <<<dim3(4, 16, 4), 256>>>(x, pos, cls);
    k_avp    <<<dim3(2, 16, 16), 256>>>(qkvw);
    k_ao_sum <<<128, 256>>>(qkvb);
    k_projp  <<<dim3(32, 16), 256>>>(pw);
    k_out_sum<<<128, 256>>>(pb, out);
}